// round 2
// baseline (speedup 1.0000x reference)
#include <cuda_runtime.h>
#include <math.h>

// ---------------------------------------------------------------------------
// BidirectionalAttentionalPromptEncoder — batch-invariant (B=1) formulation,
// broadcast to all batch rows at the end.
// Dims: C=1024, T=64 (P=S), H2=512, NH=8 (hd=128), NL=2.
// ---------------------------------------------------------------------------

#define TS 64
#define CD 1024

// ----------------------------- scratch --------------------------------------
// single device-global scratch arena (float offsets)
#define OFF_X    0          // [4][64][1024] embedded seqs: p, s, flip(p), flip(s)
#define OFF_XZ   262144     // [8][64][2048] x@Wih^T + bih + bhh per scan
#define OFF_Y0   1310720    // [4][64][1024] layer0 bilstm outputs
#define OFF_Y1   1572864    // [4][64][1024] layer1 bilstm outputs
#define OFF_HB   1835008    // [2][8][512] double-buffered h
#define OFF_CS   1843200    // [8][512] c state (contiguous after HB)
#define OFF_G0   1847296    // [2][64][2048] gate concat inputs
#define OFF_GH   2109440    // [2][64][1024]
#define OFF_GH2  2240512    // [2][64][1024]
#define OFF_GG   2371584    // [2][64][2048]
#define OFF_BI   2633728    // [2][64][1024] pbi, sbi
#define OFF_Q    2764800    // [2][64][1024]
#define OFF_K    2895872
#define OFF_V    3026944
#define OFF_AO   3158016    // attention head-concat output
#define OFF_PA   3289088    // attention projected output
#define OFF_LNO  3420160
#define OFF_T1   3551232    // [2][64][2048]
#define OFF_T2   3813376    // [2][64][2048]
#define OFF_T3   4075520    // [2][64][1024]
#define OFF_RES  4206592    // [2][64][1024] final po_row, so_row
#define SCRATCH_TOTAL 4337664

__device__ float g_scratch[SCRATCH_TOTAL];

__device__ __forceinline__ float sigf(float x) { return 1.0f / (1.0f + expf(-x)); }

// ----------------------------- utilities ------------------------------------
__global__ void zero_kernel(float* p, int n) {
    int i = blockIdx.x * 256 + threadIdx.x;
    if (i < n) p[i] = 0.0f;
}

// ----------------------------- embedding ------------------------------------
// X[b][t][c]: b=0 prefix, 1 suffix, 2 flip(prefix), 3 flip(suffix); + sinusoid.
// PE in double so --use_fast_math cannot degrade sin/cos at |x| ~ 63.
__global__ void embed_kernel(const float* __restrict__ pre,
                             const float* __restrict__ suf) {
    int idx = blockIdx.x * 256 + threadIdx.x;   // < 4*64*1024
    int b = idx >> 16;
    int t = (idx >> 10) & 63;
    int c = idx & 1023;
    int st = (b >= 2) ? (63 - t) : t;           // source time index
    const float* e = (b & 1) ? suf : pre;
    int i2 = c & ~1;
    double div = exp(-log(10000.0) * (double)i2 / 1024.0);
    double ang = (double)st * div;
    float pe = (c & 1) ? (float)cos(ang) : (float)sin(ang);
    g_scratch[OFF_X + idx] = e[st * 1024 + c] + pe;
}

// ------------------------------- GEMM ---------------------------------------
// C[m,n] = sum_k A[m,k]*W[n,k] + b1[n] + b2[n].  M=64 fixed, A:[64,K] rm,
// W:[N,K] rm. Tile 64x128, BK=16, 256 threads, 8x4 microtile, batched via
// by-value pointer arrays (blockIdx.y = batch).
struct GemmB {
    const float* A[8];
    const float* W[8];
    const float* b1[8];
    const float* b2[8];
    float*       O[8];
};

__global__ void __launch_bounds__(256, 2) gemm_m64(GemmB p, int N, int K) {
    __shared__ __align__(16) float As[16][68];
    __shared__ __align__(16) float Ws[16][132];
    int bz = blockIdx.y;
    const float* A  = p.A[bz];
    const float* W  = p.W[bz];
    const float* b1 = p.b1[bz];
    const float* b2 = p.b2[bz];
    float*       Co = p.O[bz];
    int n0 = blockIdx.x * 128;
    int tid = threadIdx.x;
    int tx = tid & 31, ty = tid >> 5;
    int row0 = ty * 8, col0 = tx * 4;

    float acc[8][4];
#pragma unroll
    for (int i = 0; i < 8; i++)
#pragma unroll
        for (int j = 0; j < 4; j++) acc[i][j] = 0.0f;

    for (int k0 = 0; k0 < K; k0 += 16) {
        {   // A tile 64x16
            int m = tid >> 2, kq = tid & 3;
            float4 v = *(const float4*)(A + (size_t)m * K + k0 + kq * 4);
            As[kq * 4 + 0][m] = v.x; As[kq * 4 + 1][m] = v.y;
            As[kq * 4 + 2][m] = v.z; As[kq * 4 + 3][m] = v.w;
        }
#pragma unroll
        for (int l = 0; l < 2; l++) {  // W tile 128x16
            int sl = tid * 2 + l;
            int n = sl >> 2, kq = sl & 3;
            float4 v = *(const float4*)(W + (size_t)(n0 + n) * K + k0 + kq * 4);
            Ws[kq * 4 + 0][n] = v.x; Ws[kq * 4 + 1][n] = v.y;
            Ws[kq * 4 + 2][n] = v.z; Ws[kq * 4 + 3][n] = v.w;
        }
        __syncthreads();
#pragma unroll
        for (int kk = 0; kk < 16; kk++) {
            float4 a0 = *(const float4*)&As[kk][row0];
            float4 a1 = *(const float4*)&As[kk][row0 + 4];
            float4 bv = *(const float4*)&Ws[kk][col0];
            float ar[8] = {a0.x, a0.y, a0.z, a0.w, a1.x, a1.y, a1.z, a1.w};
            float br[4] = {bv.x, bv.y, bv.z, bv.w};
#pragma unroll
            for (int i = 0; i < 8; i++)
#pragma unroll
                for (int j = 0; j < 4; j++) acc[i][j] += ar[i] * br[j];
        }
        __syncthreads();
    }

#pragma unroll
    for (int i = 0; i < 8; i++) {
#pragma unroll
        for (int j = 0; j < 4; j++) {
            int n = n0 + col0 + j;
            float v = acc[i][j];
            if (b1) v += b1[n];
            if (b2) v += b2[n];
            Co[(size_t)(row0 + i) * N + n] = v;
        }
    }
}

// ------------------------------ LSTM step -----------------------------------
// One timestep for all 8 scans. scan s = seq*2 + dir (seq 0..3, dir 0..1).
// Blocks: grid = (32 unit-chunks of 16, 4 groups=(lstm,dir)); each block
// handles both sequences of its group (shared Whh read once).
__global__ void __launch_bounds__(256) lstm_step_kernel(
    const float* __restrict__ Whh, int layer, int j) {
    float* XZ = g_scratch + OFF_XZ;
    float* Hb = g_scratch + OFF_HB;
    float* Cs = g_scratch + OFF_CS;
    float* Y  = g_scratch + (layer == 0 ? OFF_Y0 : OFF_Y1);
    int g = blockIdx.y;               // lstm*2 + dir
    int lstm = g >> 1, dir = g & 1;
    int t = dir ? (63 - j) : j;
    int scanA = (lstm * 2) * 2 + dir;       // seq = lstm*2
    int scanB = (lstm * 2 + 1) * 2 + dir;   // seq = lstm*2+1
    int u0 = blockIdx.x * 16;
    const float* Wg = Whh + (size_t)((lstm * 2 + layer) * 2 + dir) * (2048 * 512);

    __shared__ __align__(16) float hA[512], hB[512];
    __shared__ float part[2][4][64];
    __shared__ float zsm[2][64];

    const float* Hprev = Hb + (j & 1) * (8 * 512);
    float*       Hnext = Hb + ((j + 1) & 1) * (8 * 512);
    int tid = threadIdx.x;
    for (int i = tid; i < 512; i += 256) {
        hA[i] = Hprev[scanA * 512 + i];
        hB[i] = Hprev[scanB * 512 + i];
    }
    __syncthreads();

    // partial dot products: 64 rows (gate*16+unit) x 4 K-quarters
    {
        int r = tid & 63;
        int pp = tid >> 6;
        int gate = r >> 4, uu = r & 15;
        int row = gate * 512 + u0 + uu;
        const float4* wr = (const float4*)(Wg + (size_t)row * 512 + pp * 128);
        const float4* a4 = (const float4*)(hA + pp * 128);
        const float4* b4 = (const float4*)(hB + pp * 128);
        float accA = 0.f, accB = 0.f;
#pragma unroll 8
        for (int i = 0; i < 32; i++) {
            float4 w = wr[i], a = a4[i], b = b4[i];
            accA += w.x * a.x + w.y * a.y + w.z * a.z + w.w * a.w;
            accB += w.x * b.x + w.y * b.y + w.z * b.z + w.w * b.w;
        }
        part[0][pp][r] = accA;
        part[1][pp][r] = accB;
    }
    __syncthreads();

    if (tid < 64) {
        int gg = tid >> 4, uu = tid & 15;
        int row = gg * 512 + u0 + uu;
        zsm[0][tid] = XZ[(size_t)(scanA * 64 + t) * 2048 + row] +
                      part[0][0][tid] + part[0][1][tid] + part[0][2][tid] + part[0][3][tid];
        zsm[1][tid] = XZ[(size_t)(scanB * 64 + t) * 2048 + row] +
                      part[1][0][tid] + part[1][1][tid] + part[1][2][tid] + part[1][3][tid];
    }
    __syncthreads();

    if (tid < 32) {
        int sB = tid >> 4, uu = tid & 15;
        int scan = sB ? scanB : scanA;
        int seq = lstm * 2 + sB;
        float zi = zsm[sB][uu];
        float zf = zsm[sB][16 + uu];
        float zg = zsm[sB][32 + uu];
        float zo = zsm[sB][48 + uu];
        float cp = Cs[scan * 512 + u0 + uu];
        float c = sigf(zf) * cp + sigf(zi) * tanhf(zg);
        float h = sigf(zo) * tanhf(c);
        Cs[scan * 512 + u0 + uu] = c;
        Hnext[scan * 512 + u0 + uu] = h;
        Y[(size_t)(seq * 64 + t) * 1024 + dir * 512 + u0 + uu] = h;
    }
}

// ------------------------- gate input / combine -----------------------------
// G0[i][t] = concat(Y1[i][t], Y1[i+2][63-t])
__global__ void gatein_kernel() {
    int idx = blockIdx.x * 256 + threadIdx.x;   // < 2*64*2048
    int i = idx >> 17;
    int rem = idx & 131071;
    int t = rem >> 11;
    int c = rem & 2047;
    const float* Y1 = g_scratch + OFF_Y1;
    float v;
    if (c < 1024) v = Y1[(size_t)(i * 64 + t) * 1024 + c];
    else          v = Y1[(size_t)((i + 2) * 64 + (63 - t)) * 1024 + (c - 1024)];
    g_scratch[OFF_G0 + idx] = v;
}

// BI = sig(GG[:, :C]) * f + sig(GG[:, C:]) * b
__global__ void combine_kernel() {
    int idx = blockIdx.x * 256 + threadIdx.x;   // < 2*64*1024
    int i = idx >> 16;
    int rem = idx & 65535;
    int t = rem >> 10;
    int c = rem & 1023;
    const float* GG = g_scratch + OFF_GG;
    const float* Y1 = g_scratch + OFF_Y1;
    float fg = sigf(GG[(size_t)i * 131072 + t * 2048 + c]);
    float bg = sigf(GG[(size_t)i * 131072 + t * 2048 + 1024 + c]);
    float f = Y1[(size_t)(i * 64 + t) * 1024 + c];
    float b = Y1[(size_t)((i + 2) * 64 + (63 - t)) * 1024 + c];
    g_scratch[OFF_BI + idx] = fg * f + bg * b;
}

// -------------------------- layernorm (+gelu, +add) -------------------------
__global__ void ln_kernel(const float* __restrict__ in, const float* __restrict__ add,
                          const float* __restrict__ gamma, const float* __restrict__ beta,
                          float* __restrict__ out, int N, int dogelu, int perhalf) {
    int row = blockIdx.x;
    const float* x = in + (size_t)row * N;
    const float* ad = add ? add + (size_t)row * N : nullptr;
    int goff = perhalf ? (row >> 6) * N : 0;
    __shared__ float red[256];
    int tid = threadIdx.x;
    float s = 0.f;
    for (int i = tid; i < N; i += 256) { float v = x[i] + (ad ? ad[i] : 0.f); s += v; }
    red[tid] = s; __syncthreads();
    for (int o = 128; o > 0; o >>= 1) { if (tid < o) red[tid] += red[tid + o]; __syncthreads(); }
    float mean = red[0] / N;
    __syncthreads();
    float v2 = 0.f;
    for (int i = tid; i < N; i += 256) {
        float v = x[i] + (ad ? ad[i] : 0.f) - mean; v2 += v * v;
    }
    red[tid] = v2; __syncthreads();
    for (int o = 128; o > 0; o >>= 1) { if (tid < o) red[tid] += red[tid + o]; __syncthreads(); }
    float inv = rsqrtf(red[0] / N + 1e-5f);
    for (int i = tid; i < N; i += 256) {
        float v = (x[i] + (ad ? ad[i] : 0.f) - mean) * inv * gamma[goff + i] + beta[goff + i];
        if (dogelu) v = 0.5f * v * (1.0f + erff(v * 0.70710678118654752f));
        out[(size_t)row * N + i] = v;
    }
}

// ----------------------------- attention core -------------------------------
// block per (head, attn): softmax(QK^T/sqrt(128)) V for 64x64x128
__global__ void __launch_bounds__(256) attn_core_kernel() {
    const int h = blockIdx.x;   // 0..7
    const int a = blockIdx.y;   // 0..1
    const float* Q = g_scratch + OFF_Q + (size_t)a * 64 * 1024;
    const float* K = g_scratch + OFF_K + (size_t)a * 64 * 1024;
    const float* V = g_scratch + OFF_V + (size_t)a * 64 * 1024;
    float* AO = g_scratch + OFF_AO + (size_t)a * 64 * 1024;
    __shared__ float KV[64][128];
    __shared__ float Ssm[64][64];
    int tid = threadIdx.x;

    for (int i = tid; i < 64 * 128; i += 256) {
        int m = i >> 7, d = i & 127;
        KV[m][d] = K[m * 1024 + h * 128 + d];
    }
    __syncthreads();
    {   // scores
        int n = tid >> 2, p = tid & 3;
        float acc[16];
#pragma unroll
        for (int i = 0; i < 16; i++) acc[i] = 0.f;
        const float* q = Q + n * 1024 + h * 128;
        for (int d = 0; d < 128; d++) {
            float qv = q[d];
#pragma unroll
            for (int i = 0; i < 16; i++) acc[i] += qv * KV[p * 16 + i][d];
        }
        const float scale = 0.08838834764831845f;  // 1/sqrt(128)
#pragma unroll
        for (int i = 0; i < 16; i++) Ssm[n][p * 16 + i] = acc[i] * scale;
    }
    __syncthreads();
    for (int i = tid; i < 64 * 128; i += 256) {    // load V over K buffer
        int m = i >> 7, d = i & 127;
        KV[m][d] = V[m * 1024 + h * 128 + d];
    }
    if (tid < 64) {                                 // softmax row
        float mx = -1e30f;
        for (int m = 0; m < 64; m++) mx = fmaxf(mx, Ssm[tid][m]);
        float sum = 0.f;
        for (int m = 0; m < 64; m++) { float e = expf(Ssm[tid][m] - mx); Ssm[tid][m] = e; sum += e; }
        float invs = 1.f / sum;
        for (int m = 0; m < 64; m++) Ssm[tid][m] *= invs;
    }
    __syncthreads();
    {   // out = attn @ V
        int n = tid >> 2, p = tid & 3;
        float acc[32];
#pragma unroll
        for (int i = 0; i < 32; i++) acc[i] = 0.f;
        for (int m = 0; m < 64; m++) {
            float w = Ssm[n][m];
#pragma unroll
            for (int i = 0; i < 32; i++) acc[i] += w * KV[m][p * 32 + i];
        }
        for (int i = 0; i < 32; i++)
            AO[n * 1024 + h * 128 + p * 32 + i] = acc[i];
    }
}

// ------------------------------ broadcast -----------------------------------
__global__ void broadcast_kernel(float* __restrict__ out, int total, int half_elems) {
    int j = blockIdx.x * 256 + threadIdx.x;
    if (j >= total) return;
    int half = j / half_elems;
    int rem = j - half * half_elems;
    int i = rem & 65535;
    out[j] = g_scratch[OFF_RES + half * 65536 + i];
}

// ------------------------------- launcher -----------------------------------
extern "C" void kernel_launch(void* const* d_in, const int* in_sizes, int n_in,
                              void* d_out, int out_size) {
    const float* prefix  = (const float*)d_in[0];
    const float* suffix  = (const float*)d_in[1];
    const float* Wih     = (const float*)d_in[2];
    const float* Whh     = (const float*)d_in[3];
    const float* bih     = (const float*)d_in[4];
    const float* bhh     = (const float*)d_in[5];
    const float* attn_w  = (const float*)d_in[6];
    const float* attn_b  = (const float*)d_in[7];
    const float* gate_w1 = (const float*)d_in[8];
    const float* gate_b1 = (const float*)d_in[9];
    const float* gate_lg = (const float*)d_in[10];
    const float* gate_lb = (const float*)d_in[11];
    const float* gate_w2 = (const float*)d_in[12];
    const float* gate_b2 = (const float*)d_in[13];
    const float* out_w1  = (const float*)d_in[14];
    const float* out_b1  = (const float*)d_in[15];
    const float* out_g1  = (const float*)d_in[16];
    const float* out_be1 = (const float*)d_in[17];
    const float* out_w2  = (const float*)d_in[18];
    const float* out_b2  = (const float*)d_in[19];
    const float* out_g2  = (const float*)d_in[20];
    const float* out_be2 = (const float*)d_in[21];
    const float* ln_g    = (const float*)d_in[22];
    const float* ln_b    = (const float*)d_in[23];
    float* out = (float*)d_out;

    float* S = nullptr;
    cudaGetSymbolAddress((void**)&S, g_scratch);
    float* X   = S + OFF_X;
    float* XZ  = S + OFF_XZ;
    float* Y0  = S + OFF_Y0;
    float* Y1  = S + OFF_Y1;
    float* G0  = S + OFF_G0;
    float* GH  = S + OFF_GH;
    float* GH2 = S + OFF_GH2;
    float* GG  = S + OFF_GG;
    float* BI  = S + OFF_BI;
    float* Qp  = S + OFF_Q;
    float* Kp  = S + OFF_K;
    float* Vp  = S + OFF_V;
    float* AO  = S + OFF_AO;
    float* PA  = S + OFF_PA;
    float* LNO = S + OFF_LNO;
    float* T1  = S + OFF_T1;
    float* T2  = S + OFF_T2;
    float* T3  = S + OFF_T3;

    // 1) embed + positional encoding (4 sequences)
    embed_kernel<<<1024, 256>>>(prefix, suffix);

    // 2) bilstm: 2 layers; per layer: batched XZ GEMM then 64 sequential steps
    for (int layer = 0; layer < 2; layer++) {
        const float* src = (layer == 0) ? X : Y0;
        GemmB gb;
        for (int s = 0; s < 8; s++) {
            int seq = s >> 1, dir = s & 1, lstm = seq >> 1;
            int wi = (lstm * 2 + layer) * 2 + dir;
            gb.A[s]  = src + (size_t)seq * 64 * 1024;
            gb.W[s]  = Wih + (size_t)wi * 2048 * 1024;
            gb.b1[s] = bih + (size_t)wi * 2048;
            gb.b2[s] = bhh + (size_t)wi * 2048;
            gb.O[s]  = XZ + (size_t)s * 64 * 2048;
        }
        gemm_m64<<<dim3(16, 8), 256>>>(gb, 2048, 1024);
        zero_kernel<<<48, 256>>>(S + OFF_HB, 12288);  // HB (2*8*512) + CS (8*512)
        for (int j = 0; j < 64; j++)
            lstm_step_kernel<<<dim3(32, 4), 256>>>(Whh, layer, j);
    }

    // 3) gates
    gatein_kernel<<<1024, 256>>>();
    {
        GemmB gb;
        for (int i = 0; i < 2; i++) {
            gb.A[i]  = G0 + (size_t)i * 64 * 2048;
            gb.W[i]  = gate_w1 + (size_t)i * 1024 * 2048;
            gb.b1[i] = gate_b1 + (size_t)i * 1024;
            gb.b2[i] = nullptr;
            gb.O[i]  = GH + (size_t)i * 64 * 1024;
        }
        gemm_m64<<<dim3(8, 2), 256>>>(gb, 1024, 2048);
    }
    ln_kernel<<<128, 256>>>(GH, nullptr, gate_lg, gate_lb, GH2, 1024, 1, 1);
    {
        GemmB gb;
        for (int i = 0; i < 2; i++) {
            gb.A[i]  = GH2 + (size_t)i * 64 * 1024;
            gb.W[i]  = gate_w2 + (size_t)i * 2048 * 1024;
            gb.b1[i] = gate_b2 + (size_t)i * 2048;
            gb.b2[i] = nullptr;
            gb.O[i]  = GG + (size_t)i * 64 * 2048;
        }
        gemm_m64<<<dim3(16, 2), 256>>>(gb, 2048, 1024);
    }
    combine_kernel<<<512, 256>>>();

    // 4) cross attention: QKV projections (batch 6), core, output proj
    {
        GemmB gb;
        for (int a = 0; a < 2; a++)
            for (int k3 = 0; k3 < 3; k3++) {
                int e = a * 3 + k3;
                int srcIdx = (k3 == 0) ? a : (1 - a);
                gb.A[e]  = BI + (size_t)srcIdx * 64 * 1024;
                gb.W[e]  = attn_w + (size_t)(a * 4 + k3) * 1024 * 1024;
                gb.b1[e] = attn_b + (size_t)(a * 4 + k3) * 1024;
                gb.b2[e] = nullptr;
                float* dst = (k3 == 0) ? Qp : (k3 == 1) ? Kp : Vp;
                gb.O[e]  = dst + (size_t)a * 64 * 1024;
            }
        gemm_m64<<<dim3(8, 6), 256>>>(gb, 1024, 1024);
    }
    attn_core_kernel<<<dim3(8, 2), 256>>>();
    {
        GemmB gb;
        for (int a = 0; a < 2; a++) {
            gb.A[a]  = AO + (size_t)a * 64 * 1024;
            gb.W[a]  = attn_w + (size_t)(a * 4 + 3) * 1024 * 1024;
            gb.b1[a] = attn_b + (size_t)(a * 4 + 3) * 1024;
            gb.b2[a] = nullptr;
            gb.O[a]  = PA + (size_t)a * 64 * 1024;
        }
        gemm_m64<<<dim3(8, 2), 256>>>(gb, 1024, 1024);
    }
    ln_kernel<<<128, 256>>>(BI, PA, ln_g, ln_b, LNO, 1024, 0, 0);

    // 5) output transforms
    {
        GemmB gb;
        for (int i = 0; i < 2; i++) {
            gb.A[i]  = LNO + (size_t)i * 64 * 1024;
            gb.W[i]  = out_w1 + (size_t)i * 2048 * 1024;
            gb.b1[i] = out_b1 + (size_t)i * 2048;
            gb.b2[i] = nullptr;
            gb.O[i]  = T1 + (size_t)i * 64 * 2048;
        }
        gemm_m64<<<dim3(16, 2), 256>>>(gb, 2048, 1024);
    }
    ln_kernel<<<128, 256>>>(T1, nullptr, out_g1, out_be1, T2, 2048, 1, 1);
    {
        GemmB gb;
        for (int i = 0; i < 2; i++) {
            gb.A[i]  = T2 + (size_t)i * 64 * 2048;
            gb.W[i]  = out_w2 + (size_t)i * 1024 * 2048;
            gb.b1[i] = out_b2 + (size_t)i * 1024;
            gb.b2[i] = nullptr;
            gb.O[i]  = T3 + (size_t)i * 64 * 1024;
        }
        gemm_m64<<<dim3(8, 2), 256>>>(gb, 1024, 2048);
    }
    ln_kernel<<<128, 256>>>(T3, nullptr, out_g2, out_be2, S + OFF_RES, 1024, 0, 1);

    // 6) broadcast B=1 result to all batch rows: out = [po (B,64,1024), so (...)]
    int half_elems = out_size / 2;
    int blocks = (out_size + 255) / 256;
    broadcast_kernel<<<blocks, 256>>>(out, out_size, half_elems);
}

// round 3
// speedup vs baseline: 1.9318x; 1.9318x over previous
#include <cuda_runtime.h>
#include <math.h>

// ---------------------------------------------------------------------------
// BidirectionalAttentionalPromptEncoder — batch-invariant (B=1) formulation.
// R3: persistent SMEM-resident-weight LSTM (1 kernel/layer, software grid
// barrier) + split-K batched GEMMs.
// ---------------------------------------------------------------------------

// ----------------------------- scratch --------------------------------------
#define OFF_X    0          // [4][64][1024]
#define OFF_XZ   262144     // [8][64][2048]
#define OFF_Y0   1310720    // [4][64][1024]
#define OFF_Y1   1572864    // [4][64][1024]
#define OFF_HB   1835008    // [2][8][512]
#define OFF_CS   1843200    // [8][512]
#define OFF_G0   1847296    // [2][64][2048]
#define OFF_GH   2109440    // [2][64][1024]
#define OFF_GH2  2240512    // [2][64][1024]
#define OFF_GG   2371584    // [2][64][2048]
#define OFF_BI   2633728    // [2][64][1024]
#define OFF_Q    2764800
#define OFF_K    2895872
#define OFF_V    3026944
#define OFF_AO   3158016
#define OFF_PA   3289088
#define OFF_LNO  3420160
#define OFF_T1   3551232    // [2][64][2048]
#define OFF_T2   3813376    // [2][64][2048]
#define OFF_T3   4075520    // [2][64][1024]
#define OFF_RES  4206592    // [2][64][1024]
#define OFF_PART 4337664    // split-K partials, 2097152 floats
#define SCRATCH_TOTAL 6434816

__device__ float g_scratch[SCRATCH_TOTAL];

// barrier state (zero-initialized; gen is monotonic so replays are safe)
__device__ unsigned g_bar_cnt;
__device__ unsigned g_bar_gen;

__device__ __forceinline__ float sigf(float x) { return 1.0f / (1.0f + expf(-x)); }

// ----------------------------- embedding ------------------------------------
__global__ void embed_kernel(const float* __restrict__ pre,
                             const float* __restrict__ suf) {
    int idx = blockIdx.x * 256 + threadIdx.x;   // < 4*64*1024
    int b = idx >> 16;
    int t = (idx >> 10) & 63;
    int c = idx & 1023;
    int st = (b >= 2) ? (63 - t) : t;
    const float* e = (b & 1) ? suf : pre;
    int i2 = c & ~1;
    double div = exp(-log(10000.0) * (double)i2 / 1024.0);
    double ang = (double)st * div;
    float pe = (c & 1) ? (float)cos(ang) : (float)sin(ang);
    g_scratch[OFF_X + idx] = e[st * 1024 + c] + pe;
}

// --------------------------- split-K GEMM -----------------------------------
// partial[kc][bz][m][n] = sum_{k in chunk kc} A[m,k]*W[n,k]
// A:[64,K] rm, W:[N,K] rm. Tile 64x128, BK=16, 256 thr, 8x4 microtile.
struct GemmSK {
    const float* A[8];
    const float* W[8];
};
struct RedB {
    const float* b1[8];
    const float* b2[8];
    float*       O[8];
};

__global__ void __launch_bounds__(256, 2) gemm_m64_sk(GemmSK p, float* part,
                                                      int N, int K, int chunkK) {
    __shared__ __align__(16) float As[16][68];
    __shared__ __align__(16) float Ws[16][132];
    int bz = blockIdx.y;
    int kc = blockIdx.z;
    const float* A = p.A[bz];
    const float* W = p.W[bz];
    int n0 = blockIdx.x * 128;
    int tid = threadIdx.x;
    int tx = tid & 31, ty = tid >> 5;
    int row0 = ty * 8, col0 = tx * 4;

    float acc[8][4];
#pragma unroll
    for (int i = 0; i < 8; i++)
#pragma unroll
        for (int j = 0; j < 4; j++) acc[i][j] = 0.0f;

    int kend = (kc + 1) * chunkK;
    for (int k0 = kc * chunkK; k0 < kend; k0 += 16) {
        {   // A tile 64x16
            int m = tid >> 2, kq = tid & 3;
            float4 v = *(const float4*)(A + (size_t)m * K + k0 + kq * 4);
            As[kq * 4 + 0][m] = v.x; As[kq * 4 + 1][m] = v.y;
            As[kq * 4 + 2][m] = v.z; As[kq * 4 + 3][m] = v.w;
        }
#pragma unroll
        for (int l = 0; l < 2; l++) {  // W tile 128x16
            int sl = tid * 2 + l;
            int n = sl >> 2, kq = sl & 3;
            float4 v = *(const float4*)(W + (size_t)(n0 + n) * K + k0 + kq * 4);
            Ws[kq * 4 + 0][n] = v.x; Ws[kq * 4 + 1][n] = v.y;
            Ws[kq * 4 + 2][n] = v.z; Ws[kq * 4 + 3][n] = v.w;
        }
        __syncthreads();
#pragma unroll
        for (int kk = 0; kk < 16; kk++) {
            float4 a0 = *(const float4*)&As[kk][row0];
            float4 a1 = *(const float4*)&As[kk][row0 + 4];
            float4 bv = *(const float4*)&Ws[kk][col0];
            float ar[8] = {a0.x, a0.y, a0.z, a0.w, a1.x, a1.y, a1.z, a1.w};
            float br[4] = {bv.x, bv.y, bv.z, bv.w};
#pragma unroll
            for (int i = 0; i < 8; i++)
#pragma unroll
                for (int j = 0; j < 4; j++) acc[i][j] += ar[i] * br[j];
        }
        __syncthreads();
    }

    float* outp = part + ((size_t)(kc * gridDim.y + bz) * 64) * N;
#pragma unroll
    for (int i = 0; i < 8; i++)
#pragma unroll
        for (int j = 0; j < 4; j++)
            outp[(size_t)(row0 + i) * N + n0 + col0 + j] = acc[i][j];
}

__global__ void reduce_bias(const float* __restrict__ part, RedB rb,
                            int N, int KS, int nBatch) {
    int bz = blockIdx.y;
    int idx = blockIdx.x * 256 + threadIdx.x;   // < 64*N
    float s = 0.f;
    size_t per = (size_t)64 * N;
    for (int ks = 0; ks < KS; ks++)
        s += part[(size_t)(ks * nBatch + bz) * per + idx];
    int n = idx & (N - 1);
    if (rb.b1[bz]) s += rb.b1[bz][n];
    if (rb.b2[bz]) s += rb.b2[bz][n];
    rb.O[bz][idx] = s;
}

// --------------------------- grid barrier -----------------------------------
__device__ __forceinline__ void grid_barrier() {
    __syncthreads();
    if (threadIdx.x == 0) {
        unsigned gen = *((volatile unsigned*)&g_bar_gen);
        __threadfence();
        if (atomicAdd(&g_bar_cnt, 1u) == gridDim.x - 1) {
            g_bar_cnt = 0;
            __threadfence();
            atomicExch(&g_bar_gen, gen + 1);
        } else {
            while (*((volatile unsigned*)&g_bar_gen) == gen) __nanosleep(32);
        }
        __threadfence();
    }
    __syncthreads();
}

// ------------------------ persistent LSTM layer ------------------------------
// 128 CTAs (1/SM, all co-resident). CTA = (group g = lstm*2+dir, unit-chunk of
// 16). Weights for the CTA's 64 gate-rows live in SMEM for all 64 timesteps.
__global__ void __launch_bounds__(256, 1) lstm_persistent(
    const float* __restrict__ Whh, int layer) {
    extern __shared__ float sw[];               // [64][516] padded rows
    float* XZ = g_scratch + OFF_XZ;
    float* Hb = g_scratch + OFF_HB;
    float* Cs = g_scratch + OFF_CS;
    float* Y  = g_scratch + (layer == 0 ? OFF_Y0 : OFF_Y1);

    int blk = blockIdx.x;
    int g = blk >> 5;                // lstm*2+dir
    int chunk = blk & 31;
    int lstm = g >> 1, dir = g & 1;
    int scanA = (lstm * 2) * 2 + dir;
    int scanB = (lstm * 2 + 1) * 2 + dir;
    int u0 = chunk * 16;
    const float* Wg = Whh + (size_t)((lstm * 2 + layer) * 2 + dir) * (2048 * 512);
    int tid = threadIdx.x;

    // load our 64 weight rows (row r = gate*16+u -> global row gate*512+u0+u)
    for (int i4 = tid; i4 < 8192; i4 += 256) {
        int r = i4 >> 7, c4 = i4 & 127;
        int grow = (r >> 4) * 512 + u0 + (r & 15);
        float4 v = *(const float4*)(Wg + (size_t)grow * 512 + c4 * 4);
        *(float4*)(sw + r * 516 + c4 * 4) = v;
    }
    // init h (buffer 0) and c for our slice
    if (tid < 32) {
        int sB = tid >> 4, uu = tid & 15;
        int scan = sB ? scanB : scanA;
        Hb[scan * 512 + u0 + uu] = 0.f;
        Cs[scan * 512 + u0 + uu] = 0.f;
    }
    grid_barrier();

    __shared__ __align__(16) float hA[512], hB[512];
    __shared__ float part[2][4][64];

    for (int j = 0; j < 64; j++) {
        int t = dir ? (63 - j) : j;
        const float* Hprev = Hb + (j & 1) * (8 * 512);
        float*       Hnext = Hb + ((j + 1) & 1) * (8 * 512);
        for (int i = tid; i < 512; i += 256) {
            hA[i] = Hprev[scanA * 512 + i];
            hB[i] = Hprev[scanB * 512 + i];
        }
        __syncthreads();
        {
            int r = tid & 63, pp = tid >> 6;
            const float4* wr = (const float4*)(sw + r * 516 + pp * 128);
            const float4* a4 = (const float4*)(hA + pp * 128);
            const float4* b4 = (const float4*)(hB + pp * 128);
            float accA = 0.f, accB = 0.f;
#pragma unroll 8
            for (int i = 0; i < 32; i++) {
                float4 w = wr[i], a = a4[i], b = b4[i];
                accA += w.x * a.x + w.y * a.y + w.z * a.z + w.w * a.w;
                accB += w.x * b.x + w.y * b.y + w.z * b.z + w.w * b.w;
            }
            part[0][pp][r] = accA;
            part[1][pp][r] = accB;
        }
        __syncthreads();
        if (tid < 32) {
            int sB = tid >> 4, uu = tid & 15;
            int scan = sB ? scanB : scanA;
            int seq = lstm * 2 + sB;
            float z[4];
#pragma unroll
            for (int gg = 0; gg < 4; gg++) {
                int rr = gg * 16 + uu;
                z[gg] = XZ[(size_t)(scan * 64 + t) * 2048 + gg * 512 + u0 + uu]
                      + part[sB][0][rr] + part[sB][1][rr]
                      + part[sB][2][rr] + part[sB][3][rr];
            }
            float cp = Cs[scan * 512 + u0 + uu];
            float c = sigf(z[1]) * cp + sigf(z[0]) * tanhf(z[2]);
            float h = sigf(z[3]) * tanhf(c);
            Cs[scan * 512 + u0 + uu] = c;
            Hnext[scan * 512 + u0 + uu] = h;
            Y[(size_t)(seq * 64 + t) * 1024 + dir * 512 + u0 + uu] = h;
        }
        grid_barrier();
    }
}

// ------------------------- gate input / combine -----------------------------
__global__ void gatein_kernel() {
    int idx = blockIdx.x * 256 + threadIdx.x;   // < 2*64*2048
    int i = idx >> 17;
    int rem = idx & 131071;
    int t = rem >> 11;
    int c = rem & 2047;
    const float* Y1 = g_scratch + OFF_Y1;
    float v;
    if (c < 1024) v = Y1[(size_t)(i * 64 + t) * 1024 + c];
    else          v = Y1[(size_t)((i + 2) * 64 + (63 - t)) * 1024 + (c - 1024)];
    g_scratch[OFF_G0 + idx] = v;
}

__global__ void combine_kernel() {
    int idx = blockIdx.x * 256 + threadIdx.x;   // < 2*64*1024
    int i = idx >> 16;
    int rem = idx & 65535;
    int t = rem >> 10;
    int c = rem & 1023;
    const float* GG = g_scratch + OFF_GG;
    const float* Y1 = g_scratch + OFF_Y1;
    float fg = sigf(GG[(size_t)i * 131072 + t * 2048 + c]);
    float bg = sigf(GG[(size_t)i * 131072 + t * 2048 + 1024 + c]);
    float f = Y1[(size_t)(i * 64 + t) * 1024 + c];
    float b = Y1[(size_t)((i + 2) * 64 + (63 - t)) * 1024 + c];
    g_scratch[OFF_BI + idx] = fg * f + bg * b;
}

// -------------------------- layernorm (+gelu, +add) -------------------------
__global__ void ln_kernel(const float* __restrict__ in, const float* __restrict__ add,
                          const float* __restrict__ gamma, const float* __restrict__ beta,
                          float* __restrict__ out, int N, int dogelu, int perhalf) {
    int row = blockIdx.x;
    const float* x = in + (size_t)row * N;
    const float* ad = add ? add + (size_t)row * N : nullptr;
    int goff = perhalf ? (row >> 6) * N : 0;
    __shared__ float red[256];
    int tid = threadIdx.x;
    float s = 0.f;
    for (int i = tid; i < N; i += 256) { float v = x[i] + (ad ? ad[i] : 0.f); s += v; }
    red[tid] = s; __syncthreads();
    for (int o = 128; o > 0; o >>= 1) { if (tid < o) red[tid] += red[tid + o]; __syncthreads(); }
    float mean = red[0] / N;
    __syncthreads();
    float v2 = 0.f;
    for (int i = tid; i < N; i += 256) {
        float v = x[i] + (ad ? ad[i] : 0.f) - mean; v2 += v * v;
    }
    red[tid] = v2; __syncthreads();
    for (int o = 128; o > 0; o >>= 1) { if (tid < o) red[tid] += red[tid + o]; __syncthreads(); }
    float inv = rsqrtf(red[0] / N + 1e-5f);
    for (int i = tid; i < N; i += 256) {
        float v = (x[i] + (ad ? ad[i] : 0.f) - mean) * inv * gamma[goff + i] + beta[goff + i];
        if (dogelu) v = 0.5f * v * (1.0f + erff(v * 0.70710678118654752f));
        out[(size_t)row * N + i] = v;
    }
}

// ----------------------------- attention core -------------------------------
__global__ void __launch_bounds__(256) attn_core_kernel() {
    const int h = blockIdx.x;   // 0..7
    const int a = blockIdx.y;   // 0..1
    const float* Q = g_scratch + OFF_Q + (size_t)a * 64 * 1024;
    const float* K = g_scratch + OFF_K + (size_t)a * 64 * 1024;
    const float* V = g_scratch + OFF_V + (size_t)a * 64 * 1024;
    float* AO = g_scratch + OFF_AO + (size_t)a * 64 * 1024;
    __shared__ float KV[64][128];
    __shared__ float Ssm[64][64];
    int tid = threadIdx.x;

    for (int i = tid; i < 64 * 128; i += 256) {
        int m = i >> 7, d = i & 127;
        KV[m][d] = K[m * 1024 + h * 128 + d];
    }
    __syncthreads();
    {
        int n = tid >> 2, p = tid & 3;
        float acc[16];
#pragma unroll
        for (int i = 0; i < 16; i++) acc[i] = 0.f;
        const float* q = Q + n * 1024 + h * 128;
        for (int d = 0; d < 128; d++) {
            float qv = q[d];
#pragma unroll
            for (int i = 0; i < 16; i++) acc[i] += qv * KV[p * 16 + i][d];
        }
        const float scale = 0.08838834764831845f;
#pragma unroll
        for (int i = 0; i < 16; i++) Ssm[n][p * 16 + i] = acc[i] * scale;
    }
    __syncthreads();
    for (int i = tid; i < 64 * 128; i += 256) {
        int m = i >> 7, d = i & 127;
        KV[m][d] = V[m * 1024 + h * 128 + d];
    }
    if (tid < 64) {
        float mx = -1e30f;
        for (int m = 0; m < 64; m++) mx = fmaxf(mx, Ssm[tid][m]);
        float sum = 0.f;
        for (int m = 0; m < 64; m++) { float e = expf(Ssm[tid][m] - mx); Ssm[tid][m] = e; sum += e; }
        float invs = 1.f / sum;
        for (int m = 0; m < 64; m++) Ssm[tid][m] *= invs;
    }
    __syncthreads();
    {
        int n = tid >> 2, p = tid & 3;
        float acc[32];
#pragma unroll
        for (int i = 0; i < 32; i++) acc[i] = 0.f;
        for (int m = 0; m < 64; m++) {
            float w = Ssm[n][m];
#pragma unroll
            for (int i = 0; i < 32; i++) acc[i] += w * KV[m][p * 32 + i];
        }
        for (int i = 0; i < 32; i++)
            AO[n * 1024 + h * 128 + p * 32 + i] = acc[i];
    }
}

// ------------------------------ broadcast -----------------------------------
__global__ void broadcast_kernel(float* __restrict__ out, int total, int half_elems) {
    int j = blockIdx.x * 256 + threadIdx.x;
    if (j >= total) return;
    int half = j / half_elems;
    int rem = j - half * half_elems;
    int i = rem & 65535;
    out[j] = g_scratch[OFF_RES + half * 65536 + i];
}

// ------------------------------- launcher -----------------------------------
extern "C" void kernel_launch(void* const* d_in, const int* in_sizes, int n_in,
                              void* d_out, int out_size) {
    const float* prefix  = (const float*)d_in[0];
    const float* suffix  = (const float*)d_in[1];
    const float* Wih     = (const float*)d_in[2];
    const float* Whh     = (const float*)d_in[3];
    const float* bih     = (const float*)d_in[4];
    const float* bhh     = (const float*)d_in[5];
    const float* attn_w  = (const float*)d_in[6];
    const float* attn_b  = (const float*)d_in[7];
    const float* gate_w1 = (const float*)d_in[8];
    const float* gate_b1 = (const float*)d_in[9];
    const float* gate_lg = (const float*)d_in[10];
    const float* gate_lb = (const float*)d_in[11];
    const float* gate_w2 = (const float*)d_in[12];
    const float* gate_b2 = (const float*)d_in[13];
    const float* out_w1  = (const float*)d_in[14];
    const float* out_b1  = (const float*)d_in[15];
    const float* out_g1  = (const float*)d_in[16];
    const float* out_be1 = (const float*)d_in[17];
    const float* out_w2  = (const float*)d_in[18];
    const float* out_b2  = (const float*)d_in[19];
    const float* out_g2  = (const float*)d_in[20];
    const float* out_be2 = (const float*)d_in[21];
    const float* ln_g    = (const float*)d_in[22];
    const float* ln_b    = (const float*)d_in[23];
    float* out = (float*)d_out;

    float* S = nullptr;
    cudaGetSymbolAddress((void**)&S, g_scratch);
    float* X    = S + OFF_X;
    float* XZ   = S + OFF_XZ;
    float* Y0   = S + OFF_Y0;
    float* Y1   = S + OFF_Y1;
    float* G0   = S + OFF_G0;
    float* GH   = S + OFF_GH;
    float* GH2  = S + OFF_GH2;
    float* GG   = S + OFF_GG;
    float* BI   = S + OFF_BI;
    float* Qp   = S + OFF_Q;
    float* Kp   = S + OFF_K;
    float* Vp   = S + OFF_V;
    float* AO   = S + OFF_AO;
    float* PA   = S + OFF_PA;
    float* LNO  = S + OFF_LNO;
    float* T1   = S + OFF_T1;
    float* T2   = S + OFF_T2;
    float* T3   = S + OFF_T3;
    float* PART = S + OFF_PART;

    static int smem_set = 0;
    if (!smem_set) {
        cudaFuncSetAttribute(lstm_persistent,
                             cudaFuncAttributeMaxDynamicSharedMemorySize, 64 * 516 * 4);
        smem_set = 1;
    }
    const int LSTM_SMEM = 64 * 516 * 4;

    // 1) embed + positional encoding
    embed_kernel<<<1024, 256>>>(prefix, suffix);

    // 2) bilstm: per layer, split-K XZ GEMM + reduce, then persistent recurrence
    for (int layer = 0; layer < 2; layer++) {
        const float* src = (layer == 0) ? X : Y0;
        GemmSK gs; RedB rb;
        for (int s = 0; s < 8; s++) {
            int seq = s >> 1, dir = s & 1, lstm = seq >> 1;
            int wi = (lstm * 2 + layer) * 2 + dir;
            gs.A[s]  = src + (size_t)seq * 64 * 1024;
            gs.W[s]  = Wih + (size_t)wi * 2048 * 1024;
            rb.b1[s] = bih + (size_t)wi * 2048;
            rb.b2[s] = bhh + (size_t)wi * 2048;
            rb.O[s]  = XZ + (size_t)s * 64 * 2048;
        }
        gemm_m64_sk<<<dim3(16, 8, 2), 256>>>(gs, PART, 2048, 1024, 512);
        reduce_bias<<<dim3(512, 8), 256>>>(PART, rb, 2048, 2, 8);
        lstm_persistent<<<128, 256, LSTM_SMEM>>>(Whh, layer);
    }

    // 3) gates
    gatein_kernel<<<1024, 256>>>();
    {
        GemmSK gs; RedB rb;
        for (int i = 0; i < 2; i++) {
            gs.A[i]  = G0 + (size_t)i * 64 * 2048;
            gs.W[i]  = gate_w1 + (size_t)i * 1024 * 2048;
            rb.b1[i] = gate_b1 + (size_t)i * 1024;
            rb.b2[i] = nullptr;
            rb.O[i]  = GH + (size_t)i * 64 * 1024;
        }
        gemm_m64_sk<<<dim3(8, 2, 16), 256>>>(gs, PART, 1024, 2048, 128);
        reduce_bias<<<dim3(256, 2), 256>>>(PART, rb, 1024, 16, 2);
    }
    ln_kernel<<<128, 256>>>(GH, nullptr, gate_lg, gate_lb, GH2, 1024, 1, 1);
    {
        GemmSK gs; RedB rb;
        for (int i = 0; i < 2; i++) {
            gs.A[i]  = GH2 + (size_t)i * 64 * 1024;
            gs.W[i]  = gate_w2 + (size_t)i * 2048 * 1024;
            rb.b1[i] = gate_b2 + (size_t)i * 2048;
            rb.b2[i] = nullptr;
            rb.O[i]  = GG + (size_t)i * 64 * 2048;
        }
        gemm_m64_sk<<<dim3(16, 2, 8), 256>>>(gs, PART, 2048, 1024, 128);
        reduce_bias<<<dim3(512, 2), 256>>>(PART, rb, 2048, 8, 2);
    }
    combine_kernel<<<512, 256>>>();

    // 4) cross attention
    {
        GemmSK gs; RedB rb;
        for (int a = 0; a < 2; a++)
            for (int k3 = 0; k3 < 3; k3++) {
                int e = a * 3 + k3;
                int srcIdx = (k3 == 0) ? a : (1 - a);
                gs.A[e]  = BI + (size_t)srcIdx * 64 * 1024;
                gs.W[e]  = attn_w + (size_t)(a * 4 + k3) * 1024 * 1024;
                rb.b1[e] = attn_b + (size_t)(a * 4 + k3) * 1024;
                rb.b2[e] = nullptr;
                float* dst = (k3 == 0) ? Qp : (k3 == 1) ? Kp : Vp;
                rb.O[e]  = dst + (size_t)a * 64 * 1024;
            }
        gemm_m64_sk<<<dim3(8, 6, 4), 256>>>(gs, PART, 1024, 1024, 256);
        reduce_bias<<<dim3(256, 6), 256>>>(PART, rb, 1024, 4, 6);
    }
    attn_core_kernel<<<dim3(8, 2), 256>>>();
    {
        GemmSK gs; RedB rb;
        for (int a = 0; a < 2; a++) {
            gs.A[a]  = AO + (size_t)a * 64 * 1024;
            gs.W[a]  = attn_w + (size_t)(a * 4 + 3) * 1024 * 1024;
            rb.b1[a] = attn_b + (size_t)(a * 4 + 3) * 1024;
            rb.b2[a] = nullptr;
            rb.O[a]  = PA + (size_t)a * 64 * 1024;
        }
        gemm_m64_sk<<<dim3(8, 2, 16), 256>>>(gs, PART, 1024, 1024, 64);
        reduce_bias<<<dim3(256, 2), 256>>>(PART, rb, 1024, 16, 2);
    }
    ln_kernel<<<128, 256>>>(BI, PA, ln_g, ln_b, LNO, 1024, 0, 0);

    // 5) output transforms
    {
        GemmSK gs; RedB rb;
        for (int i = 0; i < 2; i++) {
            gs.A[i]  = LNO + (size_t)i * 64 * 1024;
            gs.W[i]  = out_w1 + (size_t)i * 2048 * 1024;
            rb.b1[i] = out_b1 + (size_t)i * 2048;
            rb.b2[i] = nullptr;
            rb.O[i]  = T1 + (size_t)i * 64 * 2048;
        }
        gemm_m64_sk<<<dim3(16, 2, 8), 256>>>(gs, PART, 2048, 1024, 128);
        reduce_bias<<<dim3(512, 2), 256>>>(PART, rb, 2048, 8, 2);
    }
    ln_kernel<<<128, 256>>>(T1, nullptr, out_g1, out_be1, T2, 2048, 1, 1);
    {
        GemmSK gs; RedB rb;
        for (int i = 0; i < 2; i++) {
            gs.A[i]  = T2 + (size_t)i * 64 * 2048;
            gs.W[i]  = out_w2 + (size_t)i * 1024 * 2048;
            rb.b1[i] = out_b2 + (size_t)i * 1024;
            rb.b2[i] = nullptr;
            rb.O[i]  = T3 + (size_t)i * 64 * 1024;
        }
        gemm_m64_sk<<<dim3(8, 2, 16), 256>>>(gs, PART, 1024, 2048, 128);
        reduce_bias<<<dim3(256, 2), 256>>>(PART, rb, 1024, 16, 2);
    }
    ln_kernel<<<128, 256>>>(T3, nullptr, out_g2, out_be2, S + OFF_RES, 1024, 0, 1);

    // 6) broadcast to all batch rows
    int half_elems = out_size / 2;
    int blocks = (out_size + 255) / 256;
    broadcast_kernel<<<blocks, 256>>>(out, out_size, half_elems);
}

// round 4
// speedup vs baseline: 2.2098x; 1.1439x over previous
#include <cuda_runtime.h>
#include <math.h>

// ---------------------------------------------------------------------------
// BidirectionalAttentionalPromptEncoder — batch-invariant (B=1) formulation.
// R4: per-group (32-CTA) monotonic barriers + SMEM-resident XZ in persistent
// LSTM; split-K batched GEMMs unchanged.
// ---------------------------------------------------------------------------

// ----------------------------- scratch --------------------------------------
#define OFF_X    0          // [4][64][1024]
#define OFF_XZ   262144     // [8][64][2048]
#define OFF_Y0   1310720    // [4][64][1024]
#define OFF_Y1   1572864    // [4][64][1024]
#define OFF_HB   1835008    // [2][8][512]
#define OFF_CS   1843200    // [8][512]
#define OFF_G0   1847296    // [2][64][2048]
#define OFF_GH   2109440    // [2][64][1024]
#define OFF_GH2  2240512    // [2][64][1024]
#define OFF_GG   2371584    // [2][64][2048]
#define OFF_BI   2633728    // [2][64][1024]
#define OFF_Q    2764800
#define OFF_K    2895872
#define OFF_V    3026944
#define OFF_AO   3158016
#define OFF_PA   3289088
#define OFF_LNO  3420160
#define OFF_T1   3551232    // [2][64][2048]
#define OFF_T2   3813376    // [2][64][2048]
#define OFF_T3   4075520    // [2][64][1024]
#define OFF_RES  4206592    // [2][64][1024]
#define OFF_PART 4337664    // split-K partials
#define SCRATCH_TOTAL 6434816

__device__ float g_scratch[SCRATCH_TOTAL];

// per-group barrier counters, one cache line apart; monotonic within a launch,
// zeroed by embed_kernel at the start of every kernel_launch/replay.
__device__ unsigned g_grp_cnt[4 * 32];

__device__ __forceinline__ float sigf(float x) { return 1.0f / (1.0f + expf(-x)); }

// ----------------------------- embedding ------------------------------------
__global__ void embed_kernel(const float* __restrict__ pre,
                             const float* __restrict__ suf) {
    if (blockIdx.x == 0 && threadIdx.x < 128) g_grp_cnt[threadIdx.x] = 0;
    int idx = blockIdx.x * 256 + threadIdx.x;   // < 4*64*1024
    int b = idx >> 16;
    int t = (idx >> 10) & 63;
    int c = idx & 1023;
    int st = (b >= 2) ? (63 - t) : t;
    const float* e = (b & 1) ? suf : pre;
    int i2 = c & ~1;
    double div = exp(-log(10000.0) * (double)i2 / 1024.0);
    double ang = (double)st * div;
    float pe = (c & 1) ? (float)cos(ang) : (float)sin(ang);
    g_scratch[OFF_X + idx] = e[st * 1024 + c] + pe;
}

// --------------------------- split-K GEMM -----------------------------------
struct GemmSK {
    const float* A[8];
    const float* W[8];
};
struct RedB {
    const float* b1[8];
    const float* b2[8];
    float*       O[8];
};

__global__ void __launch_bounds__(256, 2) gemm_m64_sk(GemmSK p, float* part,
                                                      int N, int K, int chunkK) {
    __shared__ __align__(16) float As[16][68];
    __shared__ __align__(16) float Ws[16][132];
    int bz = blockIdx.y;
    int kc = blockIdx.z;
    const float* A = p.A[bz];
    const float* W = p.W[bz];
    int n0 = blockIdx.x * 128;
    int tid = threadIdx.x;
    int tx = tid & 31, ty = tid >> 5;
    int row0 = ty * 8, col0 = tx * 4;

    float acc[8][4];
#pragma unroll
    for (int i = 0; i < 8; i++)
#pragma unroll
        for (int j = 0; j < 4; j++) acc[i][j] = 0.0f;

    int kend = (kc + 1) * chunkK;
    for (int k0 = kc * chunkK; k0 < kend; k0 += 16) {
        {
            int m = tid >> 2, kq = tid & 3;
            float4 v = *(const float4*)(A + (size_t)m * K + k0 + kq * 4);
            As[kq * 4 + 0][m] = v.x; As[kq * 4 + 1][m] = v.y;
            As[kq * 4 + 2][m] = v.z; As[kq * 4 + 3][m] = v.w;
        }
#pragma unroll
        for (int l = 0; l < 2; l++) {
            int sl = tid * 2 + l;
            int n = sl >> 2, kq = sl & 3;
            float4 v = *(const float4*)(W + (size_t)(n0 + n) * K + k0 + kq * 4);
            Ws[kq * 4 + 0][n] = v.x; Ws[kq * 4 + 1][n] = v.y;
            Ws[kq * 4 + 2][n] = v.z; Ws[kq * 4 + 3][n] = v.w;
        }
        __syncthreads();
#pragma unroll
        for (int kk = 0; kk < 16; kk++) {
            float4 a0 = *(const float4*)&As[kk][row0];
            float4 a1 = *(const float4*)&As[kk][row0 + 4];
            float4 bv = *(const float4*)&Ws[kk][col0];
            float ar[8] = {a0.x, a0.y, a0.z, a0.w, a1.x, a1.y, a1.z, a1.w};
            float br[4] = {bv.x, bv.y, bv.z, bv.w};
#pragma unroll
            for (int i = 0; i < 8; i++)
#pragma unroll
                for (int j = 0; j < 4; j++) acc[i][j] += ar[i] * br[j];
        }
        __syncthreads();
    }

    float* outp = part + ((size_t)(kc * gridDim.y + bz) * 64) * N;
#pragma unroll
    for (int i = 0; i < 8; i++)
#pragma unroll
        for (int j = 0; j < 4; j++)
            outp[(size_t)(row0 + i) * N + n0 + col0 + j] = acc[i][j];
}

__global__ void reduce_bias(const float* __restrict__ part, RedB rb,
                            int N, int KS, int nBatch) {
    int bz = blockIdx.y;
    int idx = blockIdx.x * 256 + threadIdx.x;
    float s = 0.f;
    size_t per = (size_t)64 * N;
    for (int ks = 0; ks < KS; ks++)
        s += part[(size_t)(ks * nBatch + bz) * per + idx];
    int n = idx & (N - 1);
    if (rb.b1[bz]) s += rb.b1[bz][n];
    if (rb.b2[bz]) s += rb.b2[bz][n];
    rb.O[bz][idx] = s;
}

// ------------------------ persistent LSTM layer ------------------------------
// 128 CTAs (1/SM). CTA = (group g = lstm*2+dir, 16-unit chunk). Weights AND the
// CTA's XZ slice live in SMEM for all 64 timesteps. Cross-CTA h exchange syncs
// via a per-group monotonic counter barrier (32 CTAs per group).
__global__ void __launch_bounds__(256, 1) lstm_persistent(
    const float* __restrict__ Whh, int layer) {
    extern __shared__ float smem[];
    float* sw  = smem;                 // [64][516] weight rows, padded
    float* xzs = smem + 64 * 516;      // [2][64][64] xz slice (scan, t, row)

    float* XZ = g_scratch + OFF_XZ;
    float* Hb = g_scratch + OFF_HB;
    float* Cs = g_scratch + OFF_CS;
    float* Y  = g_scratch + (layer == 0 ? OFF_Y0 : OFF_Y1);

    int blk = blockIdx.x;
    int g = blk >> 5;                  // lstm*2+dir
    int chunk = blk & 31;
    int lstm = g >> 1, dir = g & 1;
    int scanA = (lstm * 2) * 2 + dir;
    int scanB = (lstm * 2 + 1) * 2 + dir;
    int u0 = chunk * 16;
    const float* Wg = Whh + (size_t)((lstm * 2 + layer) * 2 + dir) * (2048 * 512);
    int tid = threadIdx.x;
    unsigned* cnt = &g_grp_cnt[g * 32];
    unsigned bar_base = (unsigned)layer * 65u * 32u;

    // weights: row r = gate*16+u  ->  global row gate*512+u0+u
    for (int i4 = tid; i4 < 8192; i4 += 256) {
        int r = i4 >> 7, c4 = i4 & 127;
        int grow = (r >> 4) * 512 + u0 + (r & 15);
        float4 v = *(const float4*)(Wg + (size_t)grow * 512 + c4 * 4);
        *(float4*)(sw + r * 516 + c4 * 4) = v;
    }
    // xz slice: [sB][t][r]
    for (int i = tid; i < 8192; i += 256) {
        int sB = i >> 12, t = (i >> 6) & 63, r = i & 63;
        int scan = sB ? scanB : scanA;
        int row = (r >> 4) * 512 + u0 + (r & 15);
        xzs[i] = XZ[(size_t)(scan * 64 + t) * 2048 + row];
    }
    // init h (buffer 0) and c for our slice
    if (tid < 32) {
        int sB = tid >> 4, uu = tid & 15;
        int scan = sB ? scanB : scanA;
        Hb[scan * 512 + u0 + uu] = 0.f;
        Cs[scan * 512 + u0 + uu] = 0.f;
    }
    // init barrier (barrier #1)
    __syncthreads();
    if (tid == 0) {
        __threadfence();
        atomicAdd(cnt, 1u);
        unsigned tgt = bar_base + 32u;
        while (*((volatile unsigned*)cnt) < tgt) {}
        __threadfence();
    }
    __syncthreads();

    __shared__ __align__(16) float hA[512], hB[512];
    __shared__ float part[2][4][64];

    float cstate = 0.f;
    int myScan = 0, myU = 0, mySB = 0;
    if (tid < 32) {
        mySB = tid >> 4; myU = tid & 15;
        myScan = mySB ? scanB : scanA;
        cstate = 0.f;
    }

    for (int j = 0; j < 64; j++) {
        int t = dir ? (63 - j) : j;
        const float* Hprev = Hb + (j & 1) * (8 * 512);
        float*       Hnext = Hb + ((j + 1) & 1) * (8 * 512);
        for (int i = tid; i < 512; i += 256) {
            hA[i] = Hprev[scanA * 512 + i];
            hB[i] = Hprev[scanB * 512 + i];
        }
        __syncthreads();
        {
            int r = tid & 63, pp = tid >> 6;
            const float4* wr = (const float4*)(sw + r * 516 + pp * 128);
            const float4* a4 = (const float4*)(hA + pp * 128);
            const float4* b4 = (const float4*)(hB + pp * 128);
            float accA = 0.f, accB = 0.f;
#pragma unroll 8
            for (int i = 0; i < 32; i++) {
                float4 w = wr[i], a = a4[i], b = b4[i];
                accA += w.x * a.x + w.y * a.y + w.z * a.z + w.w * a.w;
                accB += w.x * b.x + w.y * b.y + w.z * b.z + w.w * b.w;
            }
            part[0][pp][r] = accA;
            part[1][pp][r] = accB;
        }
        __syncthreads();
        if (tid < 32) {
            int seq = lstm * 2 + mySB;
            float z[4];
#pragma unroll
            for (int gg = 0; gg < 4; gg++) {
                int rr = gg * 16 + myU;
                z[gg] = xzs[mySB * 4096 + t * 64 + rr]
                      + part[mySB][0][rr] + part[mySB][1][rr]
                      + part[mySB][2][rr] + part[mySB][3][rr];
            }
            float c = sigf(z[1]) * cstate + sigf(z[0]) * tanhf(z[2]);
            float h = sigf(z[3]) * tanhf(c);
            cstate = c;
            Hnext[myScan * 512 + u0 + myU] = h;
            Y[(size_t)(seq * 64 + t) * 1024 + dir * 512 + u0 + myU] = h;
        }
        // step barrier (#j+2)
        __syncthreads();
        if (tid == 0) {
            __threadfence();
            atomicAdd(cnt, 1u);
            unsigned tgt = bar_base + (unsigned)(j + 2) * 32u;
            while (*((volatile unsigned*)cnt) < tgt) {}
            __threadfence();
        }
        __syncthreads();
    }
}

// ------------------------- gate input / combine -----------------------------
__global__ void gatein_kernel() {
    int idx = blockIdx.x * 256 + threadIdx.x;   // < 2*64*2048
    int i = idx >> 17;
    int rem = idx & 131071;
    int t = rem >> 11;
    int c = rem & 2047;
    const float* Y1 = g_scratch + OFF_Y1;
    float v;
    if (c < 1024) v = Y1[(size_t)(i * 64 + t) * 1024 + c];
    else          v = Y1[(size_t)((i + 2) * 64 + (63 - t)) * 1024 + (c - 1024)];
    g_scratch[OFF_G0 + idx] = v;
}

__global__ void combine_kernel() {
    int idx = blockIdx.x * 256 + threadIdx.x;   // < 2*64*1024
    int i = idx >> 16;
    int rem = idx & 65535;
    int t = rem >> 10;
    int c = rem & 1023;
    const float* GG = g_scratch + OFF_GG;
    const float* Y1 = g_scratch + OFF_Y1;
    float fg = sigf(GG[(size_t)i * 131072 + t * 2048 + c]);
    float bg = sigf(GG[(size_t)i * 131072 + t * 2048 + 1024 + c]);
    float f = Y1[(size_t)(i * 64 + t) * 1024 + c];
    float b = Y1[(size_t)((i + 2) * 64 + (63 - t)) * 1024 + c];
    g_scratch[OFF_BI + idx] = fg * f + bg * b;
}

// -------------------------- layernorm (+gelu, +add) -------------------------
__global__ void ln_kernel(const float* __restrict__ in, const float* __restrict__ add,
                          const float* __restrict__ gamma, const float* __restrict__ beta,
                          float* __restrict__ out, int N, int dogelu, int perhalf) {
    int row = blockIdx.x;
    const float* x = in + (size_t)row * N;
    const float* ad = add ? add + (size_t)row * N : nullptr;
    int goff = perhalf ? (row >> 6) * N : 0;
    __shared__ float red[256];
    int tid = threadIdx.x;
    float s = 0.f;
    for (int i = tid; i < N; i += 256) { float v = x[i] + (ad ? ad[i] : 0.f); s += v; }
    red[tid] = s; __syncthreads();
    for (int o = 128; o > 0; o >>= 1) { if (tid < o) red[tid] += red[tid + o]; __syncthreads(); }
    float mean = red[0] / N;
    __syncthreads();
    float v2 = 0.f;
    for (int i = tid; i < N; i += 256) {
        float v = x[i] + (ad ? ad[i] : 0.f) - mean; v2 += v * v;
    }
    red[tid] = v2; __syncthreads();
    for (int o = 128; o > 0; o >>= 1) { if (tid < o) red[tid] += red[tid + o]; __syncthreads(); }
    float inv = rsqrtf(red[0] / N + 1e-5f);
    for (int i = tid; i < N; i += 256) {
        float v = (x[i] + (ad ? ad[i] : 0.f) - mean) * inv * gamma[goff + i] + beta[goff + i];
        if (dogelu) v = 0.5f * v * (1.0f + erff(v * 0.70710678118654752f));
        out[(size_t)row * N + i] = v;
    }
}

// ----------------------------- attention core -------------------------------
__global__ void __launch_bounds__(256) attn_core_kernel() {
    const int h = blockIdx.x;
    const int a = blockIdx.y;
    const float* Q = g_scratch + OFF_Q + (size_t)a * 64 * 1024;
    const float* K = g_scratch + OFF_K + (size_t)a * 64 * 1024;
    const float* V = g_scratch + OFF_V + (size_t)a * 64 * 1024;
    float* AO = g_scratch + OFF_AO + (size_t)a * 64 * 1024;
    __shared__ float KV[64][128];
    __shared__ float Ssm[64][64];
    int tid = threadIdx.x;

    for (int i = tid; i < 64 * 128; i += 256) {
        int m = i >> 7, d = i & 127;
        KV[m][d] = K[m * 1024 + h * 128 + d];
    }
    __syncthreads();
    {
        int n = tid >> 2, p = tid & 3;
        float acc[16];
#pragma unroll
        for (int i = 0; i < 16; i++) acc[i] = 0.f;
        const float* q = Q + n * 1024 + h * 128;
        for (int d = 0; d < 128; d++) {
            float qv = q[d];
#pragma unroll
            for (int i = 0; i < 16; i++) acc[i] += qv * KV[p * 16 + i][d];
        }
        const float scale = 0.08838834764831845f;
#pragma unroll
        for (int i = 0; i < 16; i++) Ssm[n][p * 16 + i] = acc[i] * scale;
    }
    __syncthreads();
    for (int i = tid; i < 64 * 128; i += 256) {
        int m = i >> 7, d = i & 127;
        KV[m][d] = V[m * 1024 + h * 128 + d];
    }
    if (tid < 64) {
        float mx = -1e30f;
        for (int m = 0; m < 64; m++) mx = fmaxf(mx, Ssm[tid][m]);
        float sum = 0.f;
        for (int m = 0; m < 64; m++) { float e = expf(Ssm[tid][m] - mx); Ssm[tid][m] = e; sum += e; }
        float invs = 1.f / sum;
        for (int m = 0; m < 64; m++) Ssm[tid][m] *= invs;
    }
    __syncthreads();
    {
        int n = tid >> 2, p = tid & 3;
        float acc[32];
#pragma unroll
        for (int i = 0; i < 32; i++) acc[i] = 0.f;
        for (int m = 0; m < 64; m++) {
            float w = Ssm[n][m];
#pragma unroll
            for (int i = 0; i < 32; i++) acc[i] += w * KV[m][p * 32 + i];
        }
        for (int i = 0; i < 32; i++)
            AO[n * 1024 + h * 128 + p * 32 + i] = acc[i];
    }
}

// ------------------------------ broadcast -----------------------------------
__global__ void broadcast_kernel(float* __restrict__ out, int total, int half_elems) {
    int j = blockIdx.x * 256 + threadIdx.x;
    if (j >= total) return;
    int half = j / half_elems;
    int rem = j - half * half_elems;
    int i = rem & 65535;
    out[j] = g_scratch[OFF_RES + half * 65536 + i];
}

// ------------------------------- launcher -----------------------------------
extern "C" void kernel_launch(void* const* d_in, const int* in_sizes, int n_in,
                              void* d_out, int out_size) {
    const float* prefix  = (const float*)d_in[0];
    const float* suffix  = (const float*)d_in[1];
    const float* Wih     = (const float*)d_in[2];
    const float* Whh     = (const float*)d_in[3];
    const float* bih     = (const float*)d_in[4];
    const float* bhh     = (const float*)d_in[5];
    const float* attn_w  = (const float*)d_in[6];
    const float* attn_b  = (const float*)d_in[7];
    const float* gate_w1 = (const float*)d_in[8];
    const float* gate_b1 = (const float*)d_in[9];
    const float* gate_lg = (const float*)d_in[10];
    const float* gate_lb = (const float*)d_in[11];
    const float* gate_w2 = (const float*)d_in[12];
    const float* gate_b2 = (const float*)d_in[13];
    const float* out_w1  = (const float*)d_in[14];
    const float* out_b1  = (const float*)d_in[15];
    const float* out_g1  = (const float*)d_in[16];
    const float* out_be1 = (const float*)d_in[17];
    const float* out_w2  = (const float*)d_in[18];
    const float* out_b2  = (const float*)d_in[19];
    const float* out_g2  = (const float*)d_in[20];
    const float* out_be2 = (const float*)d_in[21];
    const float* ln_g    = (const float*)d_in[22];
    const float* ln_b    = (const float*)d_in[23];
    float* out = (float*)d_out;

    float* S = nullptr;
    cudaGetSymbolAddress((void**)&S, g_scratch);
    float* X    = S + OFF_X;
    float* XZ   = S + OFF_XZ;
    float* Y0   = S + OFF_Y0;
    float* G0   = S + OFF_G0;
    float* GH   = S + OFF_GH;
    float* GH2  = S + OFF_GH2;
    float* GG   = S + OFF_GG;
    float* BI   = S + OFF_BI;
    float* Qp   = S + OFF_Q;
    float* Kp   = S + OFF_K;
    float* Vp   = S + OFF_V;
    float* AO   = S + OFF_AO;
    float* PA   = S + OFF_PA;
    float* LNO  = S + OFF_LNO;
    float* T1   = S + OFF_T1;
    float* T2   = S + OFF_T2;
    float* T3   = S + OFF_T3;
    float* PART = S + OFF_PART;

    const int LSTM_SMEM = (64 * 516 + 8192) * 4;   // weights + xz slice
    static int smem_set = 0;
    if (!smem_set) {
        cudaFuncSetAttribute(lstm_persistent,
                             cudaFuncAttributeMaxDynamicSharedMemorySize, LSTM_SMEM);
        smem_set = 1;
    }

    // 1) embed + PE (also zeroes barrier counters)
    embed_kernel<<<1024, 256>>>(prefix, suffix);

    // 2) bilstm
    for (int layer = 0; layer < 2; layer++) {
        const float* src = (layer == 0) ? X : Y0;
        GemmSK gs; RedB rb;
        for (int s = 0; s < 8; s++) {
            int seq = s >> 1, dir = s & 1, lstm = seq >> 1;
            int wi = (lstm * 2 + layer) * 2 + dir;
            gs.A[s]  = src + (size_t)seq * 64 * 1024;
            gs.W[s]  = Wih + (size_t)wi * 2048 * 1024;
            rb.b1[s] = bih + (size_t)wi * 2048;
            rb.b2[s] = bhh + (size_t)wi * 2048;
            rb.O[s]  = XZ + (size_t)s * 64 * 2048;
        }
        gemm_m64_sk<<<dim3(16, 8, 2), 256>>>(gs, PART, 2048, 1024, 512);
        reduce_bias<<<dim3(512, 8), 256>>>(PART, rb, 2048, 2, 8);
        lstm_persistent<<<128, 256, LSTM_SMEM>>>(Whh, layer);
    }

    // 3) gates
    gatein_kernel<<<1024, 256>>>();
    {
        GemmSK gs; RedB rb;
        for (int i = 0; i < 2; i++) {
            gs.A[i]  = G0 + (size_t)i * 64 * 2048;
            gs.W[i]  = gate_w1 + (size_t)i * 1024 * 2048;
            rb.b1[i] = gate_b1 + (size_t)i * 1024;
            rb.b2[i] = nullptr;
            rb.O[i]  = GH + (size_t)i * 64 * 1024;
        }
        gemm_m64_sk<<<dim3(8, 2, 16), 256>>>(gs, PART, 1024, 2048, 128);
        reduce_bias<<<dim3(256, 2), 256>>>(PART, rb, 1024, 16, 2);
    }
    ln_kernel<<<128, 256>>>(GH, nullptr, gate_lg, gate_lb, GH2, 1024, 1, 1);
    {
        GemmSK gs; RedB rb;
        for (int i = 0; i < 2; i++) {
            gs.A[i]  = GH2 + (size_t)i * 64 * 1024;
            gs.W[i]  = gate_w2 + (size_t)i * 2048 * 1024;
            rb.b1[i] = gate_b2 + (size_t)i * 2048;
            rb.b2[i] = nullptr;
            rb.O[i]  = GG + (size_t)i * 64 * 2048;
        }
        gemm_m64_sk<<<dim3(16, 2, 8), 256>>>(gs, PART, 2048, 1024, 128);
        reduce_bias<<<dim3(512, 2), 256>>>(PART, rb, 2048, 8, 2);
    }
    combine_kernel<<<512, 256>>>();

    // 4) cross attention
    {
        GemmSK gs; RedB rb;
        for (int a = 0; a < 2; a++)
            for (int k3 = 0; k3 < 3; k3++) {
                int e = a * 3 + k3;
                int srcIdx = (k3 == 0) ? a : (1 - a);
                gs.A[e]  = BI + (size_t)srcIdx * 64 * 1024;
                gs.W[e]  = attn_w + (size_t)(a * 4 + k3) * 1024 * 1024;
                rb.b1[e] = attn_b + (size_t)(a * 4 + k3) * 1024;
                rb.b2[e] = nullptr;
                float* dst = (k3 == 0) ? Qp : (k3 == 1) ? Kp : Vp;
                rb.O[e]  = dst + (size_t)a * 64 * 1024;
            }
        gemm_m64_sk<<<dim3(8, 6, 4), 256>>>(gs, PART, 1024, 1024, 256);
        reduce_bias<<<dim3(256, 6), 256>>>(PART, rb, 1024, 4, 6);
    }
    attn_core_kernel<<<dim3(8, 2), 256>>>();
    {
        GemmSK gs; RedB rb;
        for (int a = 0; a < 2; a++) {
            gs.A[a]  = AO + (size_t)a * 64 * 1024;
            gs.W[a]  = attn_w + (size_t)(a * 4 + 3) * 1024 * 1024;
            rb.b1[a] = attn_b + (size_t)(a * 4 + 3) * 1024;
            rb.b2[a] = nullptr;
            rb.O[a]  = PA + (size_t)a * 64 * 1024;
        }
        gemm_m64_sk<<<dim3(8, 2, 16), 256>>>(gs, PART, 1024, 1024, 64);
        reduce_bias<<<dim3(256, 2), 256>>>(PART, rb, 1024, 16, 2);
    }
    ln_kernel<<<128, 256>>>(BI, PA, ln_g, ln_b, LNO, 1024, 0, 0);

    // 5) output transforms
    {
        GemmSK gs; RedB rb;
        for (int i = 0; i < 2; i++) {
            gs.A[i]  = LNO + (size_t)i * 64 * 1024;
            gs.W[i]  = out_w1 + (size_t)i * 2048 * 1024;
            rb.b1[i] = out_b1 + (size_t)i * 2048;
            rb.b2[i] = nullptr;
            rb.O[i]  = T1 + (size_t)i * 64 * 2048;
        }
        gemm_m64_sk<<<dim3(16, 2, 8), 256>>>(gs, PART, 2048, 1024, 128);
        reduce_bias<<<dim3(512, 2), 256>>>(PART, rb, 2048, 8, 2);
    }
    ln_kernel<<<128, 256>>>(T1, nullptr, out_g1, out_be1, T2, 2048, 1, 1);
    {
        GemmSK gs; RedB rb;
        for (int i = 0; i < 2; i++) {
            gs.A[i]  = T2 + (size_t)i * 64 * 2048;
            gs.W[i]  = out_w2 + (size_t)i * 1024 * 2048;
            rb.b1[i] = out_b2 + (size_t)i * 1024;
            rb.b2[i] = nullptr;
            rb.O[i]  = T3 + (size_t)i * 64 * 1024;
        }
        gemm_m64_sk<<<dim3(8, 2, 16), 256>>>(gs, PART, 1024, 2048, 128);
        reduce_bias<<<dim3(256, 2), 256>>>(PART, rb, 1024, 16, 2);
    }
    ln_kernel<<<128, 256>>>(T3, nullptr, out_g2, out_be2, S + OFF_RES, 1024, 0, 1);

    // 6) broadcast to all batch rows
    int half_elems = out_size / 2;
    int blocks = (out_size + 255) / 256;
    broadcast_kernel<<<blocks, 256>>>(out, out_size, half_elems);
}

// round 5
// speedup vs baseline: 2.7068x; 1.2249x over previous
#include <cuda_runtime.h>
#include <math.h>
#include <stdint.h>

// ---------------------------------------------------------------------------
// BidirectionalAttentionalPromptEncoder — batch-invariant (B=1) formulation.
// R5: LSTM barrier via red.release/ld.acquire (no MEMBAR/L1 flush) + tf32
// tensor-core GEMMs (mma.m16n8k8).
// ---------------------------------------------------------------------------

// ----------------------------- scratch --------------------------------------
#define OFF_X    0          // [4][64][1024]
#define OFF_XZ   262144     // [8][64][2048]
#define OFF_Y0   1310720    // [4][64][1024]
#define OFF_Y1   1572864    // [4][64][1024]
#define OFF_HB   1835008    // [2][8][512]
#define OFF_G0   1847296    // [2][64][2048]
#define OFF_GH   2109440    // [2][64][1024]
#define OFF_GH2  2240512    // [2][64][1024]
#define OFF_GG   2371584    // [2][64][2048]
#define OFF_BI   2633728    // [2][64][1024]
#define OFF_Q    2764800
#define OFF_K    2895872
#define OFF_V    3026944
#define OFF_AO   3158016
#define OFF_PA   3289088
#define OFF_LNO  3420160
#define OFF_T1   3551232    // [2][64][2048]
#define OFF_T2   3813376    // [2][64][2048]
#define OFF_T3   4075520    // [2][64][1024]
#define OFF_RES  4206592    // [2][64][1024]
#define OFF_PART 4337664    // split-K partials
#define SCRATCH_TOTAL 6434816

__device__ float g_scratch[SCRATCH_TOTAL];

// per-group barrier counters, one cache line apart; monotonic within a launch,
// zeroed by embed_kernel at the start of every launch/replay.
__device__ unsigned g_grp_cnt[4 * 32];

__device__ __forceinline__ float sigf(float x) { return 1.0f / (1.0f + expf(-x)); }

__device__ __forceinline__ void bar_red_release(unsigned* cnt) {
    asm volatile("red.release.gpu.global.add.u32 [%0], %1;"
                 :: "l"(cnt), "r"(1u) : "memory");
}
__device__ __forceinline__ unsigned ld_acquire(unsigned* p) {
    unsigned v;
    asm volatile("ld.acquire.gpu.global.u32 %0, [%1];"
                 : "=r"(v) : "l"(p) : "memory");
    return v;
}
__device__ __forceinline__ uint32_t f2tf32(float x) {
    uint32_t r; asm("cvt.rna.tf32.f32 %0, %1;" : "=r"(r) : "f"(x)); return r;
}

// ----------------------------- embedding ------------------------------------
__global__ void embed_kernel(const float* __restrict__ pre,
                             const float* __restrict__ suf) {
    if (blockIdx.x == 0 && threadIdx.x < 128) g_grp_cnt[threadIdx.x] = 0;
    int idx = blockIdx.x * 256 + threadIdx.x;   // < 4*64*1024
    int b = idx >> 16;
    int t = (idx >> 10) & 63;
    int c = idx & 1023;
    int st = (b >= 2) ? (63 - t) : t;
    const float* e = (b & 1) ? suf : pre;
    int i2 = c & ~1;
    double div = exp(-log(10000.0) * (double)i2 / 1024.0);
    double ang = (double)st * div;
    float pe = (c & 1) ? (float)cos(ang) : (float)sin(ang);
    g_scratch[OFF_X + idx] = e[st * 1024 + c] + pe;
}

// --------------------------- tf32 tensor GEMM -------------------------------
// partial[kc][bz] = A[64,K] · W[N,K]^T over K-chunk kc. Block tile 64x128,
// 8 warps: warp = (mt 0..3 [16 rows], nh 0..1 [64 cols]); mma.m16n8k8 tf32.
struct GemmSK {
    const float* A[8];
    const float* W[8];
};
struct RedB {
    const float* b1[8];
    const float* b2[8];
    float*       O[8];
};

__global__ void __launch_bounds__(256, 2) gemm_tc(GemmSK p, float* part,
                                                  int N, int K, int chunkK) {
    __shared__ uint32_t As[64][20];
    __shared__ uint32_t Ws[128][20];
    int bz = blockIdx.y, kc = blockIdx.z;
    const float* A = p.A[bz];
    const float* W = p.W[bz];
    int n0 = blockIdx.x * 128;
    int tid = threadIdx.x;
    int warp = tid >> 5, lane = tid & 31;
    int mt = warp & 3, nh = warp >> 2;
    int gid = lane >> 2, tig = lane & 3;

    float c[8][4];
#pragma unroll
    for (int i = 0; i < 8; i++)
#pragma unroll
        for (int j = 0; j < 4; j++) c[i][j] = 0.0f;

    int kbeg = kc * chunkK, kend = kbeg + chunkK;
    for (int k0 = kbeg; k0 < kend; k0 += 16) {
        {   // A tile 64x16 -> tf32
            int m = tid >> 2, kq = (tid & 3) * 4;
            float4 v = *(const float4*)(A + (size_t)m * K + k0 + kq);
            uint4 u = make_uint4(f2tf32(v.x), f2tf32(v.y), f2tf32(v.z), f2tf32(v.w));
            *(uint4*)&As[m][kq] = u;
        }
#pragma unroll
        for (int l = 0; l < 2; l++) {   // W tile 128x16 -> tf32
            int s = tid * 2 + l;
            int n = s >> 2, kq = (s & 3) * 4;
            float4 v = *(const float4*)(W + (size_t)(n0 + n) * K + k0 + kq);
            uint4 u = make_uint4(f2tf32(v.x), f2tf32(v.y), f2tf32(v.z), f2tf32(v.w));
            *(uint4*)&Ws[n][kq] = u;
        }
        __syncthreads();
#pragma unroll
        for (int ks = 0; ks < 2; ks++) {
            int kb = ks * 8;
            uint32_t a0 = As[mt * 16 + gid][kb + tig];
            uint32_t a1 = As[mt * 16 + gid + 8][kb + tig];
            uint32_t a2 = As[mt * 16 + gid][kb + tig + 4];
            uint32_t a3 = As[mt * 16 + gid + 8][kb + tig + 4];
#pragma unroll
            for (int nf = 0; nf < 8; nf++) {
                uint32_t b0 = Ws[nh * 64 + nf * 8 + gid][kb + tig];
                uint32_t b1 = Ws[nh * 64 + nf * 8 + gid][kb + tig + 4];
                asm volatile(
                    "mma.sync.aligned.m16n8k8.row.col.f32.tf32.tf32.f32 "
                    "{%0,%1,%2,%3}, {%4,%5,%6,%7}, {%8,%9}, {%0,%1,%2,%3};"
                    : "+f"(c[nf][0]), "+f"(c[nf][1]), "+f"(c[nf][2]), "+f"(c[nf][3])
                    : "r"(a0), "r"(a1), "r"(a2), "r"(a3), "r"(b0), "r"(b1));
            }
        }
        __syncthreads();
    }

    float* outp = part + (size_t)(kc * gridDim.y + bz) * 64 * N;
    int m0 = mt * 16 + gid;
    int nb = n0 + nh * 64 + tig * 2;
#pragma unroll
    for (int nf = 0; nf < 8; nf++) {
        int n = nb + nf * 8;
        *(float2*)(outp + (size_t)m0 * N + n)       = make_float2(c[nf][0], c[nf][1]);
        *(float2*)(outp + (size_t)(m0 + 8) * N + n) = make_float2(c[nf][2], c[nf][3]);
    }
}

__global__ void reduce_bias(const float* __restrict__ part, RedB rb,
                            int N, int KS, int nBatch) {
    int bz = blockIdx.y;
    int idx = blockIdx.x * 256 + threadIdx.x;
    float s = 0.f;
    size_t per = (size_t)64 * N;
    for (int ks = 0; ks < KS; ks++)
        s += part[(size_t)(ks * nBatch + bz) * per + idx];
    int n = idx & (N - 1);
    if (rb.b1[bz]) s += rb.b1[bz][n];
    if (rb.b2[bz]) s += rb.b2[bz][n];
    rb.O[bz][idx] = s;
}

// ------------------------ persistent LSTM layer ------------------------------
// 128 CTAs (1/SM). CTA = (group g = lstm*2+dir, 16-unit chunk). Weights + the
// CTA's XZ slice in SMEM for all 64 timesteps. Cross-CTA h exchange via
// release/acquire counter barrier per group (32 CTAs), h read via __ldcg.
__global__ void __launch_bounds__(256, 1) lstm_persistent(
    const float* __restrict__ Whh, int layer) {
    extern __shared__ float smem[];
    float* sw  = smem;                 // [64][516] weight rows
    float* xzs = smem + 64 * 516;      // [2][64][64]

    float* XZ = g_scratch + OFF_XZ;
    float* Hb = g_scratch + OFF_HB;
    float* Y  = g_scratch + (layer == 0 ? OFF_Y0 : OFF_Y1);

    int blk = blockIdx.x;
    int g = blk >> 5;                  // lstm*2+dir
    int chunk = blk & 31;
    int lstm = g >> 1, dir = g & 1;
    int scanA = lstm * 4 + dir;
    int scanB = lstm * 4 + 2 + dir;
    int u0 = chunk * 16;
    const float* Wg = Whh + (size_t)((lstm * 2 + layer) * 2 + dir) * (2048 * 512);
    int tid = threadIdx.x;
    unsigned* cnt = &g_grp_cnt[g * 32];
    unsigned base = (unsigned)layer * 2048u;

    // weights: row r = gate*16+u  ->  global row gate*512+u0+u
    for (int i4 = tid; i4 < 8192; i4 += 256) {
        int r = i4 >> 7, c4 = i4 & 127;
        int grow = (r >> 4) * 512 + u0 + (r & 15);
        float4 v = *(const float4*)(Wg + (size_t)grow * 512 + c4 * 4);
        *(float4*)(sw + r * 516 + c4 * 4) = v;
    }
    // xz slice: [sB][t][r]
    for (int i = tid; i < 8192; i += 256) {
        int sB = i >> 12, t = (i >> 6) & 63, r = i & 63;
        int scan = sB ? scanB : scanA;
        int row = (r >> 4) * 512 + u0 + (r & 15);
        xzs[i] = XZ[(size_t)(scan * 64 + t) * 2048 + row];
    }
    // init h buffer 0 for our slice
    if (tid < 32) {
        int sB = tid >> 4, uu = tid & 15;
        int scan = sB ? scanB : scanA;
        Hb[scan * 512 + u0 + uu] = 0.f;
    }
    __syncthreads();
    if (tid == 0) {
        bar_red_release(cnt);
        unsigned tgt = base + 32u;
        while (ld_acquire(cnt) < tgt) {}
    }
    __syncthreads();

    __shared__ __align__(16) float hA[512], hB[512];
    __shared__ float part[2][4][64];

    // preload h for step 0
    {
        int q = tid & 127;
        const float* src = Hb + (tid < 128 ? scanA : scanB) * 512;
        float4 v = __ldcg((const float4*)src + q);
        float* dst = (tid < 128) ? hA : hB;
        *(float4*)(dst + q * 4) = v;
    }
    __syncthreads();

    float cstate = 0.f;
    int mySB = tid >> 4, myU = tid & 15;
    int myScan = mySB ? scanB : scanA;

    for (int j = 0; j < 64; j++) {
        int t = dir ? (63 - j) : j;
        {
            int r = tid & 63, pp = tid >> 6;
            const float4* wr = (const float4*)(sw + r * 516 + pp * 128);
            const float4* a4 = (const float4*)(hA + pp * 128);
            const float4* b4 = (const float4*)(hB + pp * 128);
            float accA = 0.f, accB = 0.f;
#pragma unroll 8
            for (int i = 0; i < 32; i++) {
                float4 w = wr[i], a = a4[i], b = b4[i];
                accA += w.x * a.x + w.y * a.y + w.z * a.z + w.w * a.w;
                accB += w.x * b.x + w.y * b.y + w.z * b.z + w.w * b.w;
            }
            part[0][pp][r] = accA;
            part[1][pp][r] = accB;
        }
        __syncthreads();
        float* Hnext = Hb + ((j + 1) & 1) * 4096;
        if (tid < 32) {
            float z[4];
#pragma unroll
            for (int gg = 0; gg < 4; gg++) {
                int rr = gg * 16 + myU;
                z[gg] = xzs[mySB * 4096 + t * 64 + rr]
                      + part[mySB][0][rr] + part[mySB][1][rr]
                      + part[mySB][2][rr] + part[mySB][3][rr];
            }
            float c = sigf(z[1]) * cstate + sigf(z[0]) * tanhf(z[2]);
            float h = sigf(z[3]) * tanhf(c);
            cstate = c;
            Hnext[myScan * 512 + u0 + myU] = h;
            int seq = lstm * 2 + mySB;
            Y[(size_t)(seq * 64 + t) * 1024 + dir * 512 + u0 + myU] = h;
        }
        if (j == 63) break;
        if (tid < 32) __syncwarp(0xffffffffu);     // order warp0's STGs before release
        if (tid == 0) {
            bar_red_release(cnt);
            unsigned tgt = base + (unsigned)(j + 2) * 32u;
            while (ld_acquire(cnt) < tgt) {}
        }
        __syncthreads();
        {
            const float* Hp = Hb + ((j + 1) & 1) * 4096;
            int q = tid & 127;
            const float* src = Hp + (tid < 128 ? scanA : scanB) * 512;
            float4 v = __ldcg((const float4*)src + q);
            float* dst = (tid < 128) ? hA : hB;
            *(float4*)(dst + q * 4) = v;
        }
        __syncthreads();
    }
}

// ------------------------- gate input / combine -----------------------------
__global__ void gatein_kernel() {
    int idx = blockIdx.x * 256 + threadIdx.x;   // < 2*64*2048
    int i = idx >> 17;
    int rem = idx & 131071;
    int t = rem >> 11;
    int c = rem & 2047;
    const float* Y1 = g_scratch + OFF_Y1;
    float v;
    if (c < 1024) v = Y1[(size_t)(i * 64 + t) * 1024 + c];
    else          v = Y1[(size_t)((i + 2) * 64 + (63 - t)) * 1024 + (c - 1024)];
    g_scratch[OFF_G0 + idx] = v;
}

__global__ void combine_kernel() {
    int idx = blockIdx.x * 256 + threadIdx.x;   // < 2*64*1024
    int i = idx >> 16;
    int rem = idx & 65535;
    int t = rem >> 10;
    int c = rem & 1023;
    const float* GG = g_scratch + OFF_GG;
    const float* Y1 = g_scratch + OFF_Y1;
    float fg = sigf(GG[(size_t)i * 131072 + t * 2048 + c]);
    float bg = sigf(GG[(size_t)i * 131072 + t * 2048 + 1024 + c]);
    float f = Y1[(size_t)(i * 64 + t) * 1024 + c];
    float b = Y1[(size_t)((i + 2) * 64 + (63 - t)) * 1024 + c];
    g_scratch[OFF_BI + idx] = fg * f + bg * b;
}

// -------------------------- layernorm (+gelu, +add) -------------------------
__global__ void ln_kernel(const float* __restrict__ in, const float* __restrict__ add,
                          const float* __restrict__ gamma, const float* __restrict__ beta,
                          float* __restrict__ out, int N, int dogelu, int perhalf) {
    int row = blockIdx.x;
    const float* x = in + (size_t)row * N;
    const float* ad = add ? add + (size_t)row * N : nullptr;
    int goff = perhalf ? (row >> 6) * N : 0;
    __shared__ float red[256];
    int tid = threadIdx.x;
    float s = 0.f;
    for (int i = tid; i < N; i += 256) { float v = x[i] + (ad ? ad[i] : 0.f); s += v; }
    red[tid] = s; __syncthreads();
    for (int o = 128; o > 0; o >>= 1) { if (tid < o) red[tid] += red[tid + o]; __syncthreads(); }
    float mean = red[0] / N;
    __syncthreads();
    float v2 = 0.f;
    for (int i = tid; i < N; i += 256) {
        float v = x[i] + (ad ? ad[i] : 0.f) - mean; v2 += v * v;
    }
    red[tid] = v2; __syncthreads();
    for (int o = 128; o > 0; o >>= 1) { if (tid < o) red[tid] += red[tid + o]; __syncthreads(); }
    float inv = rsqrtf(red[0] / N + 1e-5f);
    for (int i = tid; i < N; i += 256) {
        float v = (x[i] + (ad ? ad[i] : 0.f) - mean) * inv * gamma[goff + i] + beta[goff + i];
        if (dogelu) v = 0.5f * v * (1.0f + erff(v * 0.70710678118654752f));
        out[(size_t)row * N + i] = v;
    }
}

// ----------------------------- attention core -------------------------------
__global__ void __launch_bounds__(256) attn_core_kernel() {
    const int h = blockIdx.x;
    const int a = blockIdx.y;
    const float* Q = g_scratch + OFF_Q + (size_t)a * 64 * 1024;
    const float* K = g_scratch + OFF_K + (size_t)a * 64 * 1024;
    const float* V = g_scratch + OFF_V + (size_t)a * 64 * 1024;
    float* AO = g_scratch + OFF_AO + (size_t)a * 64 * 1024;
    __shared__ float KV[64][128];
    __shared__ float Ssm[64][64];
    int tid = threadIdx.x;

    for (int i = tid; i < 64 * 128; i += 256) {
        int m = i >> 7, d = i & 127;
        KV[m][d] = K[m * 1024 + h * 128 + d];
    }
    __syncthreads();
    {
        int n = tid >> 2, p = tid & 3;
        float acc[16];
#pragma unroll
        for (int i = 0; i < 16; i++) acc[i] = 0.f;
        const float* q = Q + n * 1024 + h * 128;
        for (int d = 0; d < 128; d++) {
            float qv = q[d];
#pragma unroll
            for (int i = 0; i < 16; i++) acc[i] += qv * KV[p * 16 + i][d];
        }
        const float scale = 0.08838834764831845f;
#pragma unroll
        for (int i = 0; i < 16; i++) Ssm[n][p * 16 + i] = acc[i] * scale;
    }
    __syncthreads();
    for (int i = tid; i < 64 * 128; i += 256) {
        int m = i >> 7, d = i & 127;
        KV[m][d] = V[m * 1024 + h * 128 + d];
    }
    if (tid < 64) {
        float mx = -1e30f;
        for (int m = 0; m < 64; m++) mx = fmaxf(mx, Ssm[tid][m]);
        float sum = 0.f;
        for (int m = 0; m < 64; m++) { float e = expf(Ssm[tid][m] - mx); Ssm[tid][m] = e; sum += e; }
        float invs = 1.f / sum;
        for (int m = 0; m < 64; m++) Ssm[tid][m] *= invs;
    }
    __syncthreads();
    {
        int n = tid >> 2, p = tid & 3;
        float acc[32];
#pragma unroll
        for (int i = 0; i < 32; i++) acc[i] = 0.f;
        for (int m = 0; m < 64; m++) {
            float w = Ssm[n][m];
#pragma unroll
            for (int i = 0; i < 32; i++) acc[i] += w * KV[m][p * 32 + i];
        }
        for (int i = 0; i < 32; i++)
            AO[n * 1024 + h * 128 + p * 32 + i] = acc[i];
    }
}

// ------------------------------ broadcast -----------------------------------
__global__ void broadcast_kernel(float* __restrict__ out, int total, int half_elems) {
    int j = blockIdx.x * 256 + threadIdx.x;
    if (j >= total) return;
    int half = j / half_elems;
    int rem = j - half * half_elems;
    int i = rem & 65535;
    out[j] = g_scratch[OFF_RES + half * 65536 + i];
}

// ------------------------------- launcher -----------------------------------
extern "C" void kernel_launch(void* const* d_in, const int* in_sizes, int n_in,
                              void* d_out, int out_size) {
    const float* prefix  = (const float*)d_in[0];
    const float* suffix  = (const float*)d_in[1];
    const float* Wih     = (const float*)d_in[2];
    const float* Whh     = (const float*)d_in[3];
    const float* bih     = (const float*)d_in[4];
    const float* bhh     = (const float*)d_in[5];
    const float* attn_w  = (const float*)d_in[6];
    const float* attn_b  = (const float*)d_in[7];
    const float* gate_w1 = (const float*)d_in[8];
    const float* gate_b1 = (const float*)d_in[9];
    const float* gate_lg = (const float*)d_in[10];
    const float* gate_lb = (const float*)d_in[11];
    const float* gate_w2 = (const float*)d_in[12];
    const float* gate_b2 = (const float*)d_in[13];
    const float* out_w1  = (const float*)d_in[14];
    const float* out_b1  = (const float*)d_in[15];
    const float* out_g1  = (const float*)d_in[16];
    const float* out_be1 = (const float*)d_in[17];
    const float* out_w2  = (const float*)d_in[18];
    const float* out_b2  = (const float*)d_in[19];
    const float* out_g2  = (const float*)d_in[20];
    const float* out_be2 = (const float*)d_in[21];
    const float* ln_g    = (const float*)d_in[22];
    const float* ln_b    = (const float*)d_in[23];
    float* out = (float*)d_out;

    float* S = nullptr;
    cudaGetSymbolAddress((void**)&S, g_scratch);
    float* X    = S + OFF_X;
    float* XZ   = S + OFF_XZ;
    float* Y0   = S + OFF_Y0;
    float* G0   = S + OFF_G0;
    float* GH   = S + OFF_GH;
    float* GH2  = S + OFF_GH2;
    float* GG   = S + OFF_GG;
    float* BI   = S + OFF_BI;
    float* Qp   = S + OFF_Q;
    float* Kp   = S + OFF_K;
    float* Vp   = S + OFF_V;
    float* AO   = S + OFF_AO;
    float* PA   = S + OFF_PA;
    float* LNO  = S + OFF_LNO;
    float* T1   = S + OFF_T1;
    float* T2   = S + OFF_T2;
    float* T3   = S + OFF_T3;
    float* PART = S + OFF_PART;

    const int LSTM_SMEM = (64 * 516 + 8192) * 4;
    static int smem_set = 0;
    if (!smem_set) {
        cudaFuncSetAttribute(lstm_persistent,
                             cudaFuncAttributeMaxDynamicSharedMemorySize, LSTM_SMEM);
        smem_set = 1;
    }

    // 1) embed + PE (zeroes barrier counters)
    embed_kernel<<<1024, 256>>>(prefix, suffix);

    // 2) bilstm
    for (int layer = 0; layer < 2; layer++) {
        const float* src = (layer == 0) ? X : Y0;
        GemmSK gs; RedB rb;
        for (int s = 0; s < 8; s++) {
            int seq = s >> 1, dir = s & 1, lstm = seq >> 1;
            int wi = (lstm * 2 + layer) * 2 + dir;
            gs.A[s]  = src + (size_t)seq * 64 * 1024;
            gs.W[s]  = Wih + (size_t)wi * 2048 * 1024;
            rb.b1[s] = bih + (size_t)wi * 2048;
            rb.b2[s] = bhh + (size_t)wi * 2048;
            rb.O[s]  = XZ + (size_t)s * 64 * 2048;
        }
        gemm_tc<<<dim3(16, 8, 2), 256>>>(gs, PART, 2048, 1024, 512);
        reduce_bias<<<dim3(512, 8), 256>>>(PART, rb, 2048, 2, 8);
        lstm_persistent<<<128, 256, LSTM_SMEM>>>(Whh, layer);
    }

    // 3) gates
    gatein_kernel<<<1024, 256>>>();
    {
        GemmSK gs; RedB rb;
        for (int i = 0; i < 2; i++) {
            gs.A[i]  = G0 + (size_t)i * 64 * 2048;
            gs.W[i]  = gate_w1 + (size_t)i * 1024 * 2048;
            rb.b1[i] = gate_b1 + (size_t)i * 1024;
            rb.b2[i] = nullptr;
            rb.O[i]  = GH + (size_t)i * 64 * 1024;
        }
        gemm_tc<<<dim3(8, 2, 16), 256>>>(gs, PART, 1024, 2048, 128);
        reduce_bias<<<dim3(256, 2), 256>>>(PART, rb, 1024, 16, 2);
    }
    ln_kernel<<<128, 256>>>(GH, nullptr, gate_lg, gate_lb, GH2, 1024, 1, 1);
    {
        GemmSK gs; RedB rb;
        for (int i = 0; i < 2; i++) {
            gs.A[i]  = GH2 + (size_t)i * 64 * 1024;
            gs.W[i]  = gate_w2 + (size_t)i * 2048 * 1024;
            rb.b1[i] = gate_b2 + (size_t)i * 2048;
            rb.b2[i] = nullptr;
            rb.O[i]  = GG + (size_t)i * 64 * 2048;
        }
        gemm_tc<<<dim3(16, 2, 8), 256>>>(gs, PART, 2048, 1024, 128);
        reduce_bias<<<dim3(512, 2), 256>>>(PART, rb, 2048, 8, 2);
    }
    combine_kernel<<<512, 256>>>();

    // 4) cross attention
    {
        GemmSK gs; RedB rb;
        for (int a = 0; a < 2; a++)
            for (int k3 = 0; k3 < 3; k3++) {
                int e = a * 3 + k3;
                int srcIdx = (k3 == 0) ? a : (1 - a);
                gs.A[e]  = BI + (size_t)srcIdx * 64 * 1024;
                gs.W[e]  = attn_w + (size_t)(a * 4 + k3) * 1024 * 1024;
                rb.b1[e] = attn_b + (size_t)(a * 4 + k3) * 1024;
                rb.b2[e] = nullptr;
                float* dst = (k3 == 0) ? Qp : (k3 == 1) ? Kp : Vp;
                rb.O[e]  = dst + (size_t)a * 64 * 1024;
            }
        gemm_tc<<<dim3(8, 6, 4), 256>>>(gs, PART, 1024, 1024, 256);
        reduce_bias<<<dim3(256, 6), 256>>>(PART, rb, 1024, 4, 6);
    }
    attn_core_kernel<<<dim3(8, 2), 256>>>();
    {
        GemmSK gs; RedB rb;
        for (int a = 0; a < 2; a++) {
            gs.A[a]  = AO + (size_t)a * 64 * 1024;
            gs.W[a]  = attn_w + (size_t)(a * 4 + 3) * 1024 * 1024;
            rb.b1[a] = attn_b + (size_t)(a * 4 + 3) * 1024;
            rb.b2[a] = nullptr;
            rb.O[a]  = PA + (size_t)a * 64 * 1024;
        }
        gemm_tc<<<dim3(8, 2, 16), 256>>>(gs, PART, 1024, 1024, 64);
        reduce_bias<<<dim3(256, 2), 256>>>(PART, rb, 1024, 16, 2);
    }
    ln_kernel<<<128, 256>>>(BI, PA, ln_g, ln_b, LNO, 1024, 0, 0);

    // 5) output transforms
    {
        GemmSK gs; RedB rb;
        for (int i = 0; i < 2; i++) {
            gs.A[i]  = LNO + (size_t)i * 64 * 1024;
            gs.W[i]  = out_w1 + (size_t)i * 2048 * 1024;
            rb.b1[i] = out_b1 + (size_t)i * 2048;
            rb.b2[i] = nullptr;
            rb.O[i]  = T1 + (size_t)i * 64 * 2048;
        }
        gemm_tc<<<dim3(16, 2, 8), 256>>>(gs, PART, 2048, 1024, 128);
        reduce_bias<<<dim3(512, 2), 256>>>(PART, rb, 2048, 8, 2);
    }
    ln_kernel<<<128, 256>>>(T1, nullptr, out_g1, out_be1, T2, 2048, 1, 1);
    {
        GemmSK gs; RedB rb;
        for (int i = 0; i < 2; i++) {
            gs.A[i]  = T2 + (size_t)i * 64 * 2048;
            gs.W[i]  = out_w2 + (size_t)i * 1024 * 2048;
            rb.b1[i] = out_b2 + (size_t)i * 1024;
            rb.b2[i] = nullptr;
            rb.O[i]  = T3 + (size_t)i * 64 * 1024;
        }
        gemm_tc<<<dim3(8, 2, 16), 256>>>(gs, PART, 1024, 2048, 128);
        reduce_bias<<<dim3(256, 2), 256>>>(PART, rb, 1024, 16, 2);
    }
    ln_kernel<<<128, 256>>>(T3, nullptr, out_g2, out_be2, S + OFF_RES, 1024, 0, 1);

    // 6) broadcast to all batch rows
    int half_elems = out_size / 2;
    int blocks = (out_size + 255) / 256;
    broadcast_kernel<<<blocks, 256>>>(out, out_size, half_elems);
}